// round 10
// baseline (speedup 1.0000x reference)
#include <cuda_runtime.h>
#include <cuda_fp16.h>
#include <math.h>
#include <stdint.h>

// ---------------- problem constants ----------------
#define NN      100000
#define NE      800000
#define DD      64
#define RM      8
#define NM      5000
#define NRE     40000
#define RR      4
#define NB      1024
#define DH      512
#define DO      703

// ---------------- scratch ----------------
__device__ __half g_hW [(size_t)RM * NN * DD];   // 102.4 MB fp16
__device__ float g_h1 [(size_t)NN * DD];
__device__ float g_atts[(size_t)RM * NN];
__device__ float g_attd[(size_t)RM * NN];
__device__ float g_sum [NM];
__device__ int   g_deg   [NN];
__device__ int   g_rowptr[NN + 1];
__device__ int   g_cursor[NN];
__device__ int   g_bsum[128];
__device__ int   g_boff[130];
__device__ uint32_t g_epk[NE];
__device__ uint2 g_wfrag[(RM + RM + RR) * 4 * 8 * 32];   // B fragments for W1|W2|Wr
__device__ float g_mol [(size_t)NM * DD];
__device__ float g_molr[(size_t)NM * DD];
__device__ float g_feat[(size_t)NB * 2 * DD];
__device__ float g_hid [(size_t)NB * DH];

__device__ __forceinline__ void red_add_v4(float* p, float4 v) {
    asm volatile("red.global.add.v4.f32 [%0], {%1,%2,%3,%4};"
                 :: "l"(p), "f"(v.x), "f"(v.y), "f"(v.z), "f"(v.w) : "memory");
}
__device__ __forceinline__ void red_add_v2(float* p, float2 v) {
    asm volatile("red.global.add.v2.f32 [%0], {%1,%2};"
                 :: "l"(p), "f"(v.x), "f"(v.y) : "memory");
}

__global__ void fill_kernel(float* __restrict__ p, float v, int n) {
    int i = blockIdx.x * blockDim.x + threadIdx.x;
    if (i < n) p[i] = v;
}
__global__ void fill4_kernel(float4* __restrict__ p, int n4) {
    int i = blockIdx.x * blockDim.x + threadIdx.x;
    if (i < n4) p[i] = make_float4(0.f, 0.f, 0.f, 0.f);
}
__global__ void filli_kernel(int* __restrict__ p, int v, int n) {
    int i = blockIdx.x * blockDim.x + threadIdx.x;
    if (i < n) p[i] = v;
}

// ================= CSR build =================
__global__ void hist_kernel(const int* __restrict__ dst, int* __restrict__ deg, int E) {
    int e = blockIdx.x * blockDim.x + threadIdx.x;
    if (e < E) atomicAdd(&deg[dst[e]], 1);
}

__global__ void scan_bsum_kernel(const int* __restrict__ deg, int* __restrict__ bsum, int N) {
    int b = blockIdx.x, t = threadIdx.x;
    int base = b * 1024 + t;
    int s = 0;
    #pragma unroll
    for (int q = 0; q < 4; q++) { int i = base + q * 256; if (i < N) s += deg[i]; }
    #pragma unroll
    for (int o = 16; o; o >>= 1) s += __shfl_xor_sync(0xffffffffu, s, o);
    __shared__ int ws[8];
    if ((t & 31) == 0) ws[t >> 5] = s;
    __syncthreads();
    if (t == 0) { int tot = 0; for (int i = 0; i < 8; i++) tot += ws[i]; bsum[b] = tot; }
}

__global__ void scan_sums_kernel(const int* __restrict__ bsum, int* __restrict__ boff, int nb) {
    int t = threadIdx.x, lane = t & 31, w = t >> 5;
    int v = (t < nb) ? bsum[t] : 0;
    int inc = v;
    #pragma unroll
    for (int o = 1; o < 32; o <<= 1) {
        int nv = __shfl_up_sync(0xffffffffu, inc, o);
        if (lane >= o) inc += nv;
    }
    __shared__ int ws[4];
    if (lane == 31) ws[w] = inc;
    __syncthreads();
    int add = 0;
    for (int i = 0; i < w; i++) add += ws[i];
    if (t < nb) boff[t] = add + inc - v;
    if (t == 0) boff[nb] = ws[0] + ws[1] + ws[2] + ws[3];
}

__global__ void scan_final_kernel(const int* __restrict__ deg, const int* __restrict__ boff,
                                  int* __restrict__ rowptr, int* __restrict__ cursor, int N, int nb) {
    int b = blockIdx.x, t = threadIdx.x, lane = t & 31, wid = t >> 5;
    int idx0 = b * 1024 + t * 4;
    int v0 = 0, v1 = 0, v2 = 0, v3 = 0;
    if (idx0 + 0 < N) v0 = deg[idx0 + 0];
    if (idx0 + 1 < N) v1 = deg[idx0 + 1];
    if (idx0 + 2 < N) v2 = deg[idx0 + 2];
    if (idx0 + 3 < N) v3 = deg[idx0 + 3];
    int tot = v0 + v1 + v2 + v3;
    int inc = tot;
    #pragma unroll
    for (int o = 1; o < 32; o <<= 1) {
        int nv = __shfl_up_sync(0xffffffffu, inc, o);
        if (lane >= o) inc += nv;
    }
    __shared__ int wsum[8], woff[8];
    if (lane == 31) wsum[wid] = inc;
    __syncthreads();
    if (t == 0) { int a = 0; for (int i = 0; i < 8; i++) { woff[i] = a; a += wsum[i]; } }
    __syncthreads();
    int run = boff[b] + woff[wid] + inc - tot;
    if (idx0 + 0 < N) { rowptr[idx0 + 0] = run; cursor[idx0 + 0] = run; } run += v0;
    if (idx0 + 1 < N) { rowptr[idx0 + 1] = run; cursor[idx0 + 1] = run; } run += v1;
    if (idx0 + 2 < N) { rowptr[idx0 + 2] = run; cursor[idx0 + 2] = run; } run += v2;
    if (idx0 + 3 < N) { rowptr[idx0 + 3] = run; cursor[idx0 + 3] = run; }
    if (b == 0 && t == 0) rowptr[N] = boff[nb];
}

__global__ void scatter_kernel(const int* __restrict__ src, const int* __restrict__ dst,
                               const int* __restrict__ rel,
                               int* __restrict__ cursor, uint32_t* __restrict__ epk, int E) {
    int e = blockIdx.x * blockDim.x + threadIdx.x;
    if (e >= E) return;
    int pos = atomicAdd(&cursor[dst[e]], 1);
    epk[pos] = (uint32_t)src[e] | ((uint32_t)rel[e] << 20);
}

// ================= warp-MMA helpers =================
__device__ __forceinline__ uint32_t smem_u32(const void* p) {
    return (uint32_t)__cvta_generic_to_shared(p);
}
#define LDSM_X4(r0, r1, r2, r3, addr) \
    asm volatile("ldmatrix.sync.aligned.m8n8.x4.shared.b16 {%0,%1,%2,%3}, [%4];" \
                 : "=r"(r0), "=r"(r1), "=r"(r2), "=r"(r3) : "r"(addr))
#define LDSM_X2T(r0, r1, addr) \
    asm volatile("ldmatrix.sync.aligned.m8n8.x2.trans.shared.b16 {%0,%1}, [%2];" \
                 : "=r"(r0), "=r"(r1) : "r"(addr))
#define MMA16816(c, a, b) \
    asm volatile("mma.sync.aligned.m16n8k16.row.col.f32.f16.f16.f32 " \
                 "{%0,%1,%2,%3}, {%4,%5,%6,%7}, {%8,%9}, {%0,%1,%2,%3};" \
                 : "+f"((c)[0]), "+f"((c)[1]), "+f"((c)[2]), "+f"((c)[3]) \
                 : "r"((a)[0]), "r"((a)[1]), "r"((a)[2]), "r"((a)[3]), \
                   "r"((b)[0]), "r"((b)[1]))

// ---------------- precompute B fragments for all W sets ----------------
// grid = RM + RM + RR blocks of 32 threads; block b handles one relation matrix.
__global__ void prep_wfrag_kernel(const float* __restrict__ W1, const float* __restrict__ W2,
                                  const float* __restrict__ Wr, uint2* __restrict__ frag)
{
    __shared__ __align__(16) __half sw[64 * 72];
    int b = blockIdx.x, lane = threadIdx.x;
    const float* Wsrc;
    if (b < RM)            Wsrc = W1 + (size_t)b * 4096;
    else if (b < 2 * RM)   Wsrc = W2 + (size_t)(b - RM) * 4096;
    else                   Wsrc = Wr + (size_t)(b - 2 * RM) * 4096;

    for (int i = lane; i < 4096; i += 32)
        sw[(i >> 6) * 72 + (i & 63)] = __float2half(Wsrc[i]);
    __syncwarp();

    #pragma unroll
    for (int kk = 0; kk < 4; kk++)
        #pragma unroll
        for (int j = 0; j < 8; j++) {
            uint32_t b0, b1;
            uint32_t addr = smem_u32(&sw[(kk * 16 + (lane & 15)) * 72 + j * 8]);
            LDSM_X2T(b0, b1, addr);
            frag[((size_t)(b * 4 + kk) * 8 + j) * 32 + lane] = make_uint2(b0, b1);
        }
}

// ---------------- hW GEMM on HMMA, B frags from global ----------------
// No per-relation syncthreads: B frags via coalesced LDG (L1-hot),
// output staging reuses the (dead) h-tile smem, warp-private rows.
__global__ __launch_bounds__(128)
void hw_mma_kernel(const float* __restrict__ h,
                   const uint2* __restrict__ wfrag,
                   const float* __restrict__ a_src,
                   const float* __restrict__ a_dst,
                   __half* __restrict__ hW,
                   float* __restrict__ att_s,
                   float* __restrict__ att_d,
                   int N, int R)
{
    __shared__ __align__(16) __half sa[128 * 72];   // h tile, later output staging
    __shared__ float sas[8 * 64], sad[8 * 64];

    const int tid  = threadIdx.x;
    const int wid  = tid >> 5;
    const int lane = tid & 31;
    const int n0   = blockIdx.x * 128;

    for (int i = tid; i < R * 64; i += 128) { sas[i] = a_src[i]; sad[i] = a_dst[i]; }

    // h tile: fp32 -> fp16, stride 72
    #pragma unroll
    for (int it = 0; it < 8; it++) {
        int chunk = it * 128 + tid;
        int row = chunk >> 3;
        int c8  = (chunk & 7) * 8;
        int n = n0 + row;
        float4 a = make_float4(0.f,0.f,0.f,0.f), b = a;
        if (n < N) {
            a = *(const float4*)&h[(size_t)n * 64 + c8];
            b = *(const float4*)&h[(size_t)n * 64 + c8 + 4];
        }
        __half2 pk[4];
        pk[0] = __floats2half2_rn(a.x, a.y);
        pk[1] = __floats2half2_rn(a.z, a.w);
        pk[2] = __floats2half2_rn(b.x, b.y);
        pk[3] = __floats2half2_rn(b.z, b.w);
        *(uint4*)&sa[row * 72 + c8] = *(uint4*)pk;
    }
    __syncthreads();

    // A fragments (warp reads ONLY its own 32 rows)
    uint32_t afrag[2][4][4];
    {
        const int l15 = lane & 15;
        const int lhi = lane >> 4;
        #pragma unroll
        for (int mt = 0; mt < 2; mt++)
            #pragma unroll
            for (int kk = 0; kk < 4; kk++) {
                uint32_t addr = smem_u32(&sa[(wid * 32 + mt * 16 + l15) * 72 + kk * 16 + lhi * 8]);
                LDSM_X4(afrag[mt][kk][0], afrag[mt][kk][1],
                        afrag[mt][kk][2], afrag[mt][kk][3], addr);
            }
    }
    // after this point each warp only touches its own 32 rows of sa -> no block sync needed

    const int t4 = lane >> 2;
    const int t2 = (lane & 3) * 2;

    for (int r = 0; r < R; r++) {
        float c[2][8][4];
        #pragma unroll
        for (int mt = 0; mt < 2; mt++)
            #pragma unroll
            for (int j = 0; j < 8; j++)
                #pragma unroll
                for (int q = 0; q < 4; q++) c[mt][j][q] = 0.f;

        #pragma unroll
        for (int kk = 0; kk < 4; kk++) {
            uint32_t b[8][2];
            #pragma unroll
            for (int j = 0; j < 8; j++) {
                uint2 f = __ldg(&wfrag[((size_t)(r * 4 + kk) * 8 + j) * 32 + lane]);
                b[j][0] = f.x; b[j][1] = f.y;
            }
            #pragma unroll
            for (int mt = 0; mt < 2; mt++)
                #pragma unroll
                for (int j = 0; j < 8; j++)
                    MMA16816(c[mt][j], afrag[mt][kk], b[j]);
        }

        // ---- fused attention logits ----
        #pragma unroll
        for (int mt = 0; mt < 2; mt++) {
            float ps0 = 0.f, pd0 = 0.f, ps1 = 0.f, pd1 = 0.f;
            #pragma unroll
            for (int j = 0; j < 8; j++) {
                float as0 = sas[r * 64 + j * 8 + t2], as1 = sas[r * 64 + j * 8 + t2 + 1];
                float ad0 = sad[r * 64 + j * 8 + t2], ad1 = sad[r * 64 + j * 8 + t2 + 1];
                ps0 += c[mt][j][0] * as0 + c[mt][j][1] * as1;
                pd0 += c[mt][j][0] * ad0 + c[mt][j][1] * ad1;
                ps1 += c[mt][j][2] * as0 + c[mt][j][3] * as1;
                pd1 += c[mt][j][2] * ad0 + c[mt][j][3] * ad1;
            }
            #pragma unroll
            for (int o = 1; o <= 2; o <<= 1) {
                ps0 += __shfl_xor_sync(0xffffffffu, ps0, o);
                pd0 += __shfl_xor_sync(0xffffffffu, pd0, o);
                ps1 += __shfl_xor_sync(0xffffffffu, ps1, o);
                pd1 += __shfl_xor_sync(0xffffffffu, pd1, o);
            }
            if ((lane & 3) == 0) {
                int n1 = n0 + wid * 32 + mt * 16 + t4;
                int n2 = n1 + 8;
                if (n1 < N) { att_s[(size_t)r * N + n1] = ps0; att_d[(size_t)r * N + n1] = pd0; }
                if (n2 < N) { att_s[(size_t)r * N + n2] = ps1; att_d[(size_t)r * N + n2] = pd1; }
            }
        }

        // ---- warp-private staging (own 32 rows of sa) + coalesced store ----
        #pragma unroll
        for (int mt = 0; mt < 2; mt++) {
            int rr = wid * 32 + mt * 16 + t4;
            #pragma unroll
            for (int j = 0; j < 8; j++) {
                *(__half2*)&sa[rr * 72 + j * 8 + t2]       = __floats2half2_rn(c[mt][j][0], c[mt][j][1]);
                *(__half2*)&sa[(rr + 8) * 72 + j * 8 + t2] = __floats2half2_rn(c[mt][j][2], c[mt][j][3]);
            }
        }
        __syncwarp();
        #pragma unroll
        for (int it = 0; it < 8; it++) {
            int idx = it * 32 + lane;
            int rowl = idx >> 3;
            int q    = idx & 7;
            int row  = wid * 32 + rowl;
            int n = n0 + row;
            if (n < N)
                *(uint4*)&hW[((size_t)r * N + n) * 64 + q * 8] = *(uint4*)&sa[row * 72 + q * 8];
        }
        __syncwarp();   // stores done before next relation overwrites staging
    }
}

// ---------------- CSR edge aggregation: one warp per dst, 4-edge unroll ----------------
template<bool SEG>
__global__ void edge_agg_kernel(const int* __restrict__ rowptr, const uint32_t* __restrict__ epk,
                                const float* __restrict__ att_s, const float* __restrict__ att_d,
                                const __half* __restrict__ hW, const int* __restrict__ seg,
                                float* __restrict__ outh, int N, int R)
{
    int w = (blockIdx.x * blockDim.x + threadIdx.x) >> 5;
    int lane = threadIdx.x & 31;
    if (w >= N) return;
    int beg = rowptr[w], end = rowptr[w + 1];
    float adv = (lane < R) ? att_d[(size_t)lane * N + w] : 0.f;
    float acc0 = 0.f, acc1 = 0.f, ssum = 0.f;
    int e = beg;
    for (; e + 3 < end; e += 4) {
        uint32_t p0 = epk[e], p1 = epk[e + 1], p2 = epk[e + 2], p3 = epk[e + 3];
        int s0 = p0 & 0xFFFFF, r0 = p0 >> 20;
        int s1 = p1 & 0xFFFFF, r1 = p1 >> 20;
        int s2 = p2 & 0xFFFFF, r2 = p2 >> 20;
        int s3 = p3 & 0xFFFFF, r3 = p3 >> 20;
        float sc0 = att_s[(size_t)r0 * N + s0] + __shfl_sync(0xffffffffu, adv, r0);
        float sc1 = att_s[(size_t)r1 * N + s1] + __shfl_sync(0xffffffffu, adv, r1);
        float sc2 = att_s[(size_t)r2 * N + s2] + __shfl_sync(0xffffffffu, adv, r2);
        float sc3 = att_s[(size_t)r3 * N + s3] + __shfl_sync(0xffffffffu, adv, r3);
        sc0 = (sc0 > 0.f) ? sc0 : 0.2f * sc0;
        sc1 = (sc1 > 0.f) ? sc1 : 0.2f * sc1;
        sc2 = (sc2 > 0.f) ? sc2 : 0.2f * sc2;
        sc3 = (sc3 > 0.f) ? sc3 : 0.2f * sc3;
        float x0 = __expf(sc0), x1 = __expf(sc1), x2 = __expf(sc2), x3 = __expf(sc3);
        __half2 h0 = *(const __half2*)&hW[((size_t)r0 * N + s0) * 64 + lane * 2];
        __half2 h1 = *(const __half2*)&hW[((size_t)r1 * N + s1) * 64 + lane * 2];
        __half2 h2 = *(const __half2*)&hW[((size_t)r2 * N + s2) * 64 + lane * 2];
        __half2 h3 = *(const __half2*)&hW[((size_t)r3 * N + s3) * 64 + lane * 2];
        float2 f0 = __half22float2(h0), f1 = __half22float2(h1);
        float2 f2 = __half22float2(h2), f3 = __half22float2(h3);
        acc0 = fmaf(x0, f0.x, acc0); acc1 = fmaf(x0, f0.y, acc1);
        acc0 = fmaf(x1, f1.x, acc0); acc1 = fmaf(x1, f1.y, acc1);
        acc0 = fmaf(x2, f2.x, acc0); acc1 = fmaf(x2, f2.y, acc1);
        acc0 = fmaf(x3, f3.x, acc0); acc1 = fmaf(x3, f3.y, acc1);
        ssum += (x0 + x1) + (x2 + x3);
    }
    for (; e < end; e++) {
        uint32_t p0 = epk[e];
        int s0 = p0 & 0xFFFFF, r0 = p0 >> 20;
        float sc0 = att_s[(size_t)r0 * N + s0] + __shfl_sync(0xffffffffu, adv, r0);
        sc0 = (sc0 > 0.f) ? sc0 : 0.2f * sc0;
        float x0 = __expf(sc0);
        __half2 h0 = *(const __half2*)&hW[((size_t)r0 * N + s0) * 64 + lane * 2];
        float2 f0 = __half22float2(h0);
        acc0 = fmaf(x0, f0.x, acc0); acc1 = fmaf(x0, f0.y, acc1);
        ssum += x0;
    }
    float inv = 1.f / (ssum + 1e-9f);
    float v0 = acc0 * inv, v1 = acc1 * inv;
    v0 = (v0 > 0.f) ? v0 : expm1f(v0);
    v1 = (v1 > 0.f) ? v1 : expm1f(v1);
    if (SEG) {
        red_add_v2(&outh[(size_t)seg[w] * 64 + lane * 2], make_float2(v0, v1));
    } else {
        *(float2*)&outh[(size_t)w * 64 + lane * 2] = make_float2(v0, v1);
    }
}

// ---------------- atomic edge path (reaction graph only) ----------------
__global__ void edge_fused_kernel(const int* __restrict__ src, const int* __restrict__ dst,
                                  const int* __restrict__ rel,
                                  const float* __restrict__ att_s, const float* __restrict__ att_d,
                                  const __half* __restrict__ hW,
                                  float* __restrict__ dsum, float* __restrict__ agg,
                                  int E, int N)
{
    int t = blockIdx.x * blockDim.x + threadIdx.x;
    int e = t >> 3;
    if (e >= E) return;
    int g = t & 7;
    int s = src[e], d = dst[e], r = rel[e];
    float v = att_s[(size_t)r * N + s] + att_d[(size_t)r * N + d];
    v = (v > 0.f) ? v : 0.2f * v;
    float x = __expf(v);

    uint4 raw = *(const uint4*)&hW[((size_t)r * N + s) * 64 + g * 8];
    __half2* hp = (__half2*)&raw;
    float2 f0 = __half22float2(hp[0]);
    float2 f1 = __half22float2(hp[1]);
    float2 f2 = __half22float2(hp[2]);
    float2 f3 = __half22float2(hp[3]);

    float* base = &agg[(size_t)d * 64 + g * 8];
    red_add_v4(base,     make_float4(x * f0.x, x * f0.y, x * f1.x, x * f1.y));
    red_add_v4(base + 4, make_float4(x * f2.x, x * f2.y, x * f3.x, x * f3.y));
    if (g == 0) atomicAdd(&dsum[d], x);
}

__global__ void norm_elu_seg_kernel(const float* __restrict__ agg, const float* __restrict__ dsum,
                                    const int* __restrict__ seg, float* __restrict__ feat, int n)
{
    int t = blockIdx.x * blockDim.x + threadIdx.x;
    int i = t >> 5;
    if (i >= n) return;
    int g = (t & 31) * 2;
    float s = dsum[i];
    float inv = 1.f / (s + 1e-9f);
    float2 v = *(const float2*)&agg[(size_t)i * 64 + g];
    v.x *= inv; v.y *= inv;
    v.x = (v.x > 0.f) ? v.x : expm1f(v.x);
    v.y = (v.y > 0.f) ? v.y : expm1f(v.y);
    red_add_v2(&feat[(size_t)seg[i] * 128 + g], v);
}

__global__ void segsum_kernel(const float* __restrict__ x, const int* __restrict__ seg,
                              float* __restrict__ out, int n, int ostride, int ooff)
{
    int t = blockIdx.x * blockDim.x + threadIdx.x;
    int i = t >> 4;
    if (i >= n) return;
    int g = (t & 15) * 4;
    int s = seg[i];
    float4 v = *(const float4*)&x[(size_t)i * 64 + g];
    red_add_v4(&out[(size_t)s * ostride + ooff + g], v);
}

// ---------------- MLP head ----------------
__global__ void fc1_kernel(const float* __restrict__ feat, const float* __restrict__ w,
                           const float* __restrict__ b, const float* __restrict__ prelu,
                           float* __restrict__ out)
{
    const int r0 = blockIdx.x * 16;
    const int c0 = blockIdx.y * 128;
    __shared__ float fs[16][128];
    #pragma unroll
    for (int it = 0; it < 4; it++) {
        int idx4 = it * 128 + threadIdx.x;
        int row = idx4 >> 5, col = (idx4 & 31) * 4;
        *(float4*)&fs[row][col] = *(const float4*)&feat[(size_t)(r0 + row) * 128 + col];
    }
    __syncthreads();
    const int col = c0 + threadIdx.x;
    float acc[16];
    #pragma unroll
    for (int j = 0; j < 16; j++) acc[j] = 0.f;
    #pragma unroll 4
    for (int k = 0; k < 128; k++) {
        float wv = w[k * 512 + col];
        #pragma unroll
        for (int j = 0; j < 16; j++) acc[j] += fs[j][k] * wv;
    }
    float bb = b[col], p = prelu[0];
    #pragma unroll
    for (int j = 0; j < 16; j++) {
        float v = acc[j] + bb;
        out[(size_t)(r0 + j) * 512 + col] = (v > 0.f) ? v : p * v;
    }
}

__global__ void fc2_kernel(const float* __restrict__ hid, const float* __restrict__ w,
                           const float* __restrict__ b, float* __restrict__ out)
{
    const int r0 = blockIdx.x * 16;
    const int c0 = blockIdx.y * 128;
    __shared__ float hs[16][512];
    #pragma unroll
    for (int it = 0; it < 16; it++) {
        int idx4 = it * 128 + threadIdx.x;
        int row = idx4 >> 7, col = (idx4 & 127) * 4;
        *(float4*)&hs[row][col] = *(const float4*)&hid[(size_t)(r0 + row) * 512 + col];
    }
    __syncthreads();
    const int col = c0 + threadIdx.x;
    if (col >= DO) return;
    float acc[16];
    #pragma unroll
    for (int j = 0; j < 16; j++) acc[j] = 0.f;
    #pragma unroll 4
    for (int k = 0; k < 512; k++) {
        float wv = w[k * DO + col];
        #pragma unroll
        for (int j = 0; j < 16; j++) acc[j] += hs[j][k] * wv;
    }
    float bb = b[col];
    #pragma unroll
    for (int j = 0; j < 16; j++)
        out[(size_t)(r0 + j) * DO + col] = acc[j] + bb;
}

// ---------------- launch ----------------
static inline int cdiv(int a, int b) { return (a + b - 1) / b; }

extern "C" void kernel_launch(void* const* d_in, const int* in_sizes, int n_in,
                              void* d_out, int out_size)
{
    const float* node_feats = (const float*)d_in[0];
    const int*   edge_src   = (const int*)  d_in[1];
    const int*   edge_dst   = (const int*)  d_in[2];
    const int*   edge_rel   = (const int*)  d_in[3];
    const int*   node2mol   = (const int*)  d_in[4];
    const int*   rxn_src    = (const int*)  d_in[5];
    const int*   rxn_dst    = (const int*)  d_in[6];
    const int*   rxn_rel    = (const int*)  d_in[7];
    const int*   mol2rxn    = (const int*)  d_in[8];
    const float* W1    = (const float*)d_in[9];
    const float* as1   = (const float*)d_in[10];
    const float* ad1   = (const float*)d_in[11];
    const float* W2    = (const float*)d_in[12];
    const float* as2   = (const float*)d_in[13];
    const float* ad2   = (const float*)d_in[14];
    const float* Wr    = (const float*)d_in[15];
    const float* asr   = (const float*)d_in[16];
    const float* adr   = (const float*)d_in[17];
    const float* w_fc1 = (const float*)d_in[18];
    const float* b_fc1 = (const float*)d_in[19];
    const float* prelu = (const float*)d_in[20];
    const float* w_fc2 = (const float*)d_in[21];
    const float* b_fc2 = (const float*)d_in[22];
    float* out = (float*)d_out;

    __half* p_hW;
    float *p_h1, *p_atts, *p_attd, *p_sum, *p_mol, *p_molr, *p_feat, *p_hid;
    int *p_deg, *p_rowptr, *p_cursor, *p_bsum, *p_boff;
    uint32_t* p_epk;
    uint2* p_wfrag;
    cudaGetSymbolAddress((void**)&p_hW,    g_hW);
    cudaGetSymbolAddress((void**)&p_h1,    g_h1);
    cudaGetSymbolAddress((void**)&p_atts,  g_atts);
    cudaGetSymbolAddress((void**)&p_attd,  g_attd);
    cudaGetSymbolAddress((void**)&p_sum,   g_sum);
    cudaGetSymbolAddress((void**)&p_deg,   g_deg);
    cudaGetSymbolAddress((void**)&p_rowptr,g_rowptr);
    cudaGetSymbolAddress((void**)&p_cursor,g_cursor);
    cudaGetSymbolAddress((void**)&p_bsum,  g_bsum);
    cudaGetSymbolAddress((void**)&p_boff,  g_boff);
    cudaGetSymbolAddress((void**)&p_epk,   g_epk);
    cudaGetSymbolAddress((void**)&p_wfrag, g_wfrag);
    cudaGetSymbolAddress((void**)&p_mol,   g_mol);
    cudaGetSymbolAddress((void**)&p_molr,  g_molr);
    cudaGetSymbolAddress((void**)&p_feat,  g_feat);
    cudaGetSymbolAddress((void**)&p_hid,   g_hid);

    const int TB = 256;
    const int NBLK = cdiv(NN, 1024);   // 98
    const int FRAGS_PER_R = 4 * 8 * 32;   // 1024 uint2 per relation

    // ===== precompute B fragments + build atom CSR =====
    prep_wfrag_kernel<<<RM + RM + RR, 32>>>(W1, W2, Wr, p_wfrag);
    filli_kernel<<<cdiv(NN, TB), TB>>>(p_deg, 0, NN);
    hist_kernel<<<cdiv(NE, TB), TB>>>(edge_dst, p_deg, NE);
    scan_bsum_kernel<<<NBLK, 256>>>(p_deg, p_bsum, NN);
    scan_sums_kernel<<<1, 128>>>(p_bsum, p_boff, NBLK);
    scan_final_kernel<<<NBLK, 256>>>(p_deg, p_boff, p_rowptr, p_cursor, NN, NBLK);
    scatter_kernel<<<cdiv(NE, TB), TB>>>(edge_src, edge_dst, edge_rel, p_cursor, p_epk, NE);

    // ===== atom layer 1 =====
    hw_mma_kernel<<<cdiv(NN, 128), 128>>>(node_feats, p_wfrag, as1, ad1,
                                          p_hW, p_atts, p_attd, NN, RM);
    edge_agg_kernel<false><<<cdiv(NN * 32, TB), TB>>>(p_rowptr, p_epk, p_atts, p_attd, p_hW,
                                                      (const int*)0, p_h1, NN, RM);

    // ===== atom layer 2 (reduces straight into mol) =====
    fill4_kernel<<<cdiv(NM * 16, TB), TB>>>((float4*)p_mol, NM * 16);
    hw_mma_kernel<<<cdiv(NN, 128), 128>>>(p_h1, p_wfrag + (size_t)RM * FRAGS_PER_R, as2, ad2,
                                          p_hW, p_atts, p_attd, NN, RM);
    edge_agg_kernel<true><<<cdiv(NN * 32, TB), TB>>>(p_rowptr, p_epk, p_atts, p_attd, p_hW,
                                                     node2mol, p_mol, NN, RM);

    // ===== reaction-level RGAT =====
    fill_kernel<<<cdiv(NM, TB), TB>>>(p_sum, 0.f, NM);
    fill4_kernel<<<cdiv(NM * 16, TB), TB>>>((float4*)p_molr, NM * 16);
    fill4_kernel<<<cdiv(NB * 32, TB), TB>>>((float4*)p_feat, NB * 32);
    hw_mma_kernel<<<cdiv(NM, 128), 128>>>(p_mol, p_wfrag + (size_t)2 * RM * FRAGS_PER_R, asr, adr,
                                          p_hW, p_atts, p_attd, NM, RR);
    edge_fused_kernel<<<cdiv(NRE * 8, TB), TB>>>(rxn_src, rxn_dst, rxn_rel,
                                                 p_atts, p_attd, p_hW, p_sum, p_molr, NRE, NM);
    norm_elu_seg_kernel<<<cdiv(NM * 32, TB), TB>>>(p_molr, p_sum, mol2rxn, p_feat, NM);

    // ===== reaction readout (second half: direct mol sums) =====
    segsum_kernel<<<cdiv(NM * 16, TB), TB>>>(p_mol, mol2rxn, p_feat, NM, 128, 64);

    // ===== MLP head =====
    fc1_kernel<<<dim3(NB / 16, 4), 128>>>(p_feat, w_fc1, b_fc1, prelu, p_hid);
    fc2_kernel<<<dim3(NB / 16, 6), 128>>>(p_hid, w_fc2, b_fc2, out);
}

// round 11
// speedup vs baseline: 1.0335x; 1.0335x over previous
#include <cuda_runtime.h>
#include <cuda_fp16.h>
#include <math.h>
#include <stdint.h>

// ---------------- problem constants ----------------
#define NN      100000
#define NE      800000
#define DD      64
#define RM      8
#define NM      5000
#define NRE     40000
#define RR      4
#define NB      1024
#define DH      512
#define DO      703

// ---------------- scratch ----------------
__device__ __half g_hW [(size_t)RM * NN * DD];   // 102.4 MB fp16
__device__ float g_h1 [(size_t)NN * DD];
__device__ float g_atts[(size_t)RM * NN];
__device__ float g_attd[(size_t)RM * NN];
__device__ float g_sum [NM];
__device__ int   g_deg   [NN];
__device__ int   g_rowptr[NN + 1];
__device__ int   g_cursor[NN];
__device__ int   g_bsum[128];
__device__ int   g_boff[130];
__device__ uint32_t g_epk[NE];
__device__ float g_mol [(size_t)NM * DD];
__device__ float g_molr[(size_t)NM * DD];
__device__ float g_feat[(size_t)NB * 2 * DD];
__device__ float g_hid [(size_t)NB * DH];

__device__ __forceinline__ void red_add_v4(float* p, float4 v) {
    asm volatile("red.global.add.v4.f32 [%0], {%1,%2,%3,%4};"
                 :: "l"(p), "f"(v.x), "f"(v.y), "f"(v.z), "f"(v.w) : "memory");
}
__device__ __forceinline__ void red_add_v2(float* p, float2 v) {
    asm volatile("red.global.add.v2.f32 [%0], {%1,%2};"
                 :: "l"(p), "f"(v.x), "f"(v.y) : "memory");
}

__global__ void fill_kernel(float* __restrict__ p, float v, int n) {
    int i = blockIdx.x * blockDim.x + threadIdx.x;
    if (i < n) p[i] = v;
}
__global__ void fill4_kernel(float4* __restrict__ p, int n4) {
    int i = blockIdx.x * blockDim.x + threadIdx.x;
    if (i < n4) p[i] = make_float4(0.f, 0.f, 0.f, 0.f);
}
__global__ void filli_kernel(int* __restrict__ p, int v, int n) {
    int i = blockIdx.x * blockDim.x + threadIdx.x;
    if (i < n) p[i] = v;
}

// ================= CSR build =================
__global__ void hist_kernel(const int* __restrict__ dst, int* __restrict__ deg, int E) {
    int e = blockIdx.x * blockDim.x + threadIdx.x;
    if (e < E) atomicAdd(&deg[dst[e]], 1);
}

__global__ void scan_bsum_kernel(const int* __restrict__ deg, int* __restrict__ bsum, int N) {
    int b = blockIdx.x, t = threadIdx.x;
    int base = b * 1024 + t;
    int s = 0;
    #pragma unroll
    for (int q = 0; q < 4; q++) { int i = base + q * 256; if (i < N) s += deg[i]; }
    #pragma unroll
    for (int o = 16; o; o >>= 1) s += __shfl_xor_sync(0xffffffffu, s, o);
    __shared__ int ws[8];
    if ((t & 31) == 0) ws[t >> 5] = s;
    __syncthreads();
    if (t == 0) { int tot = 0; for (int i = 0; i < 8; i++) tot += ws[i]; bsum[b] = tot; }
}

__global__ void scan_sums_kernel(const int* __restrict__ bsum, int* __restrict__ boff, int nb) {
    int t = threadIdx.x, lane = t & 31, w = t >> 5;
    int v = (t < nb) ? bsum[t] : 0;
    int inc = v;
    #pragma unroll
    for (int o = 1; o < 32; o <<= 1) {
        int nv = __shfl_up_sync(0xffffffffu, inc, o);
        if (lane >= o) inc += nv;
    }
    __shared__ int ws[4];
    if (lane == 31) ws[w] = inc;
    __syncthreads();
    int add = 0;
    for (int i = 0; i < w; i++) add += ws[i];
    if (t < nb) boff[t] = add + inc - v;
    if (t == 0) boff[nb] = ws[0] + ws[1] + ws[2] + ws[3];
}

__global__ void scan_final_kernel(const int* __restrict__ deg, const int* __restrict__ boff,
                                  int* __restrict__ rowptr, int* __restrict__ cursor, int N, int nb) {
    int b = blockIdx.x, t = threadIdx.x, lane = t & 31, wid = t >> 5;
    int idx0 = b * 1024 + t * 4;
    int v0 = 0, v1 = 0, v2 = 0, v3 = 0;
    if (idx0 + 0 < N) v0 = deg[idx0 + 0];
    if (idx0 + 1 < N) v1 = deg[idx0 + 1];
    if (idx0 + 2 < N) v2 = deg[idx0 + 2];
    if (idx0 + 3 < N) v3 = deg[idx0 + 3];
    int tot = v0 + v1 + v2 + v3;
    int inc = tot;
    #pragma unroll
    for (int o = 1; o < 32; o <<= 1) {
        int nv = __shfl_up_sync(0xffffffffu, inc, o);
        if (lane >= o) inc += nv;
    }
    __shared__ int wsum[8], woff[8];
    if (lane == 31) wsum[wid] = inc;
    __syncthreads();
    if (t == 0) { int a = 0; for (int i = 0; i < 8; i++) { woff[i] = a; a += wsum[i]; } }
    __syncthreads();
    int run = boff[b] + woff[wid] + inc - tot;
    if (idx0 + 0 < N) { rowptr[idx0 + 0] = run; cursor[idx0 + 0] = run; } run += v0;
    if (idx0 + 1 < N) { rowptr[idx0 + 1] = run; cursor[idx0 + 1] = run; } run += v1;
    if (idx0 + 2 < N) { rowptr[idx0 + 2] = run; cursor[idx0 + 2] = run; } run += v2;
    if (idx0 + 3 < N) { rowptr[idx0 + 3] = run; cursor[idx0 + 3] = run; }
    if (b == 0 && t == 0) rowptr[N] = boff[nb];
}

__global__ void scatter_kernel(const int* __restrict__ src, const int* __restrict__ dst,
                               const int* __restrict__ rel,
                               int* __restrict__ cursor, uint32_t* __restrict__ epk, int E) {
    int e = blockIdx.x * blockDim.x + threadIdx.x;
    if (e >= E) return;
    int pos = atomicAdd(&cursor[dst[e]], 1);
    epk[pos] = (uint32_t)src[e] | ((uint32_t)rel[e] << 20);
}

// ================= warp-MMA helpers =================
__device__ __forceinline__ uint32_t smem_u32(const void* p) {
    return (uint32_t)__cvta_generic_to_shared(p);
}
#define LDSM_X4(r0, r1, r2, r3, addr) \
    asm volatile("ldmatrix.sync.aligned.m8n8.x4.shared.b16 {%0,%1,%2,%3}, [%4];" \
                 : "=r"(r0), "=r"(r1), "=r"(r2), "=r"(r3) : "r"(addr))
#define LDSM_X2T(r0, r1, addr) \
    asm volatile("ldmatrix.sync.aligned.m8n8.x2.trans.shared.b16 {%0,%1}, [%2];" \
                 : "=r"(r0), "=r"(r1) : "r"(addr))
#define MMA16816(c, a, b) \
    asm volatile("mma.sync.aligned.m16n8k16.row.col.f32.f16.f16.f32 " \
                 "{%0,%1,%2,%3}, {%4,%5,%6,%7}, {%8,%9}, {%0,%1,%2,%3};" \
                 : "+f"((c)[0]), "+f"((c)[1]), "+f"((c)[2]), "+f"((c)[3]) \
                 : "r"((a)[0]), "r"((a)[1]), "r"((a)[2]), "r"((a)[3]), \
                   "r"((b)[0]), "r"((b)[1]))

// ---------------- hW GEMM on HMMA + fused attention-logit epilogue ----------------
// Double-buffered W tile in smem (R9 version — measured best); warp-private
// output staging; one block sync per relation.
__global__ __launch_bounds__(128)
void hw_mma_kernel(const float* __restrict__ h,
                   const float* __restrict__ W,
                   const float* __restrict__ a_src,
                   const float* __restrict__ a_dst,
                   __half* __restrict__ hW,
                   float* __restrict__ att_s,
                   float* __restrict__ att_d,
                   int N, int R)
{
    __shared__ __align__(16) __half sa [128 * 72];
    __shared__ __align__(16) __half swt[2][64 * 72];
    __shared__ __align__(16) __half sc [128 * 72];
    __shared__ float sas[8 * 64], sad[8 * 64];

    const int tid  = threadIdx.x;
    const int wid  = tid >> 5;
    const int lane = tid & 31;
    const int n0   = blockIdx.x * 128;

    for (int i = tid; i < R * 64; i += 128) { sas[i] = a_src[i]; sad[i] = a_dst[i]; }

    // h tile: fp32 -> fp16, stride 72
    #pragma unroll
    for (int it = 0; it < 8; it++) {
        int chunk = it * 128 + tid;
        int row = chunk >> 3;
        int c8  = (chunk & 7) * 8;
        int n = n0 + row;
        float4 a = make_float4(0.f,0.f,0.f,0.f), b = a;
        if (n < N) {
            a = *(const float4*)&h[(size_t)n * 64 + c8];
            b = *(const float4*)&h[(size_t)n * 64 + c8 + 4];
        }
        __half2 pk[4];
        pk[0] = __floats2half2_rn(a.x, a.y);
        pk[1] = __floats2half2_rn(a.z, a.w);
        pk[2] = __floats2half2_rn(b.x, b.y);
        pk[3] = __floats2half2_rn(b.z, b.w);
        *(uint4*)&sa[row * 72 + c8] = *(uint4*)pk;
    }

    // preload W_0 into swt[0]
    {
        const float4* Wr4 = (const float4*)W;
        #pragma unroll
        for (int it = 0; it < 8; it++) {
            int i = it * 128 + tid;
            float4 f = Wr4[i];
            int k = i >> 4, c = (i & 15) * 4;
            *(__half2*)&swt[0][k * 72 + c]     = __floats2half2_rn(f.x, f.y);
            *(__half2*)&swt[0][k * 72 + c + 2] = __floats2half2_rn(f.z, f.w);
        }
    }
    __syncthreads();

    // A fragments, held across relations
    uint32_t afrag[2][4][4];
    {
        const int l15 = lane & 15;
        const int lhi = lane >> 4;
        #pragma unroll
        for (int mt = 0; mt < 2; mt++)
            #pragma unroll
            for (int kk = 0; kk < 4; kk++) {
                uint32_t addr = smem_u32(&sa[(wid * 32 + mt * 16 + l15) * 72 + kk * 16 + lhi * 8]);
                LDSM_X4(afrag[mt][kk][0], afrag[mt][kk][1],
                        afrag[mt][kk][2], afrag[mt][kk][3], addr);
            }
    }

    const int t4 = lane >> 2;
    const int t2 = (lane & 3) * 2;

    for (int r = 0; r < R; r++) {
        const int buf = r & 1;

        float c[2][8][4];
        #pragma unroll
        for (int mt = 0; mt < 2; mt++)
            #pragma unroll
            for (int j = 0; j < 8; j++)
                #pragma unroll
                for (int q = 0; q < 4; q++) c[mt][j][q] = 0.f;

        #pragma unroll
        for (int kk = 0; kk < 4; kk++) {
            uint32_t b[8][2];
            const int l15 = lane & 15;
            #pragma unroll
            for (int j = 0; j < 8; j++) {
                uint32_t addr = smem_u32(&swt[buf][(kk * 16 + l15) * 72 + j * 8]);
                LDSM_X2T(b[j][0], b[j][1], addr);
            }
            #pragma unroll
            for (int mt = 0; mt < 2; mt++)
                #pragma unroll
                for (int j = 0; j < 8; j++)
                    MMA16816(c[mt][j], afrag[mt][kk], b[j]);
        }

        // convert next relation's W into the other buffer (overlaps epilogue)
        if (r + 1 < R) {
            const float4* Wr4 = (const float4*)(W + (size_t)(r + 1) * 4096);
            #pragma unroll
            for (int it = 0; it < 8; it++) {
                int i = it * 128 + tid;
                float4 f = Wr4[i];
                int k = i >> 4, cc = (i & 15) * 4;
                *(__half2*)&swt[1 - buf][k * 72 + cc]     = __floats2half2_rn(f.x, f.y);
                *(__half2*)&swt[1 - buf][k * 72 + cc + 2] = __floats2half2_rn(f.z, f.w);
            }
        }

        // ---- fused attention logits ----
        #pragma unroll
        for (int mt = 0; mt < 2; mt++) {
            float ps0 = 0.f, pd0 = 0.f, ps1 = 0.f, pd1 = 0.f;
            #pragma unroll
            for (int j = 0; j < 8; j++) {
                float as0 = sas[r * 64 + j * 8 + t2], as1 = sas[r * 64 + j * 8 + t2 + 1];
                float ad0 = sad[r * 64 + j * 8 + t2], ad1 = sad[r * 64 + j * 8 + t2 + 1];
                ps0 += c[mt][j][0] * as0 + c[mt][j][1] * as1;
                pd0 += c[mt][j][0] * ad0 + c[mt][j][1] * ad1;
                ps1 += c[mt][j][2] * as0 + c[mt][j][3] * as1;
                pd1 += c[mt][j][2] * ad0 + c[mt][j][3] * ad1;
            }
            #pragma unroll
            for (int o = 1; o <= 2; o <<= 1) {
                ps0 += __shfl_xor_sync(0xffffffffu, ps0, o);
                pd0 += __shfl_xor_sync(0xffffffffu, pd0, o);
                ps1 += __shfl_xor_sync(0xffffffffu, ps1, o);
                pd1 += __shfl_xor_sync(0xffffffffu, pd1, o);
            }
            if ((lane & 3) == 0) {
                int n1 = n0 + wid * 32 + mt * 16 + t4;
                int n2 = n1 + 8;
                if (n1 < N) { att_s[(size_t)r * N + n1] = ps0; att_d[(size_t)r * N + n1] = pd0; }
                if (n2 < N) { att_s[(size_t)r * N + n2] = ps1; att_d[(size_t)r * N + n2] = pd1; }
            }
        }

        // ---- warp-private staging + coalesced store of own 32 rows ----
        #pragma unroll
        for (int mt = 0; mt < 2; mt++) {
            int rr = wid * 32 + mt * 16 + t4;
            #pragma unroll
            for (int j = 0; j < 8; j++) {
                *(__half2*)&sc[rr * 72 + j * 8 + t2]       = __floats2half2_rn(c[mt][j][0], c[mt][j][1]);
                *(__half2*)&sc[(rr + 8) * 72 + j * 8 + t2] = __floats2half2_rn(c[mt][j][2], c[mt][j][3]);
            }
        }
        __syncwarp();
        #pragma unroll
        for (int it = 0; it < 8; it++) {
            int idx = it * 32 + lane;
            int rowl = idx >> 3;
            int q    = idx & 7;
            int row  = wid * 32 + rowl;
            int n = n0 + row;
            if (n < N)
                *(uint4*)&hW[((size_t)r * N + n) * 64 + q * 8] = *(uint4*)&sc[row * 72 + q * 8];
        }
        __syncthreads();   // next W buffer ready; sc rows reusable
    }
}

// ---------------- CSR edge aggregation: one warp per dst, 4-edge unroll ----------------
template<bool SEG>
__global__ void edge_agg_kernel(const int* __restrict__ rowptr, const uint32_t* __restrict__ epk,
                                const float* __restrict__ att_s, const float* __restrict__ att_d,
                                const __half* __restrict__ hW, const int* __restrict__ seg,
                                float* __restrict__ outh, int N, int R)
{
    int w = (blockIdx.x * blockDim.x + threadIdx.x) >> 5;
    int lane = threadIdx.x & 31;
    if (w >= N) return;
    int beg = rowptr[w], end = rowptr[w + 1];
    float adv = (lane < R) ? att_d[(size_t)lane * N + w] : 0.f;
    float acc0 = 0.f, acc1 = 0.f, ssum = 0.f;
    int e = beg;
    for (; e + 3 < end; e += 4) {
        uint32_t p0 = epk[e], p1 = epk[e + 1], p2 = epk[e + 2], p3 = epk[e + 3];
        int s0 = p0 & 0xFFFFF, r0 = p0 >> 20;
        int s1 = p1 & 0xFFFFF, r1 = p1 >> 20;
        int s2 = p2 & 0xFFFFF, r2 = p2 >> 20;
        int s3 = p3 & 0xFFFFF, r3 = p3 >> 20;
        float sc0 = att_s[(size_t)r0 * N + s0] + __shfl_sync(0xffffffffu, adv, r0);
        float sc1 = att_s[(size_t)r1 * N + s1] + __shfl_sync(0xffffffffu, adv, r1);
        float sc2 = att_s[(size_t)r2 * N + s2] + __shfl_sync(0xffffffffu, adv, r2);
        float sc3 = att_s[(size_t)r3 * N + s3] + __shfl_sync(0xffffffffu, adv, r3);
        sc0 = (sc0 > 0.f) ? sc0 : 0.2f * sc0;
        sc1 = (sc1 > 0.f) ? sc1 : 0.2f * sc1;
        sc2 = (sc2 > 0.f) ? sc2 : 0.2f * sc2;
        sc3 = (sc3 > 0.f) ? sc3 : 0.2f * sc3;
        float x0 = __expf(sc0), x1 = __expf(sc1), x2 = __expf(sc2), x3 = __expf(sc3);
        __half2 h0 = *(const __half2*)&hW[((size_t)r0 * N + s0) * 64 + lane * 2];
        __half2 h1 = *(const __half2*)&hW[((size_t)r1 * N + s1) * 64 + lane * 2];
        __half2 h2 = *(const __half2*)&hW[((size_t)r2 * N + s2) * 64 + lane * 2];
        __half2 h3 = *(const __half2*)&hW[((size_t)r3 * N + s3) * 64 + lane * 2];
        float2 f0 = __half22float2(h0), f1 = __half22float2(h1);
        float2 f2 = __half22float2(h2), f3 = __half22float2(h3);
        acc0 = fmaf(x0, f0.x, acc0); acc1 = fmaf(x0, f0.y, acc1);
        acc0 = fmaf(x1, f1.x, acc0); acc1 = fmaf(x1, f1.y, acc1);
        acc0 = fmaf(x2, f2.x, acc0); acc1 = fmaf(x2, f2.y, acc1);
        acc0 = fmaf(x3, f3.x, acc0); acc1 = fmaf(x3, f3.y, acc1);
        ssum += (x0 + x1) + (x2 + x3);
    }
    for (; e < end; e++) {
        uint32_t p0 = epk[e];
        int s0 = p0 & 0xFFFFF, r0 = p0 >> 20;
        float sc0 = att_s[(size_t)r0 * N + s0] + __shfl_sync(0xffffffffu, adv, r0);
        sc0 = (sc0 > 0.f) ? sc0 : 0.2f * sc0;
        float x0 = __expf(sc0);
        __half2 h0 = *(const __half2*)&hW[((size_t)r0 * N + s0) * 64 + lane * 2];
        float2 f0 = __half22float2(h0);
        acc0 = fmaf(x0, f0.x, acc0); acc1 = fmaf(x0, f0.y, acc1);
        ssum += x0;
    }
    float inv = 1.f / (ssum + 1e-9f);
    float v0 = acc0 * inv, v1 = acc1 * inv;
    v0 = (v0 > 0.f) ? v0 : expm1f(v0);
    v1 = (v1 > 0.f) ? v1 : expm1f(v1);
    if (SEG) {
        red_add_v2(&outh[(size_t)seg[w] * 64 + lane * 2], make_float2(v0, v1));
    } else {
        *(float2*)&outh[(size_t)w * 64 + lane * 2] = make_float2(v0, v1);
    }
}

// ---------------- atomic edge path (reaction graph only) ----------------
__global__ void edge_fused_kernel(const int* __restrict__ src, const int* __restrict__ dst,
                                  const int* __restrict__ rel,
                                  const float* __restrict__ att_s, const float* __restrict__ att_d,
                                  const __half* __restrict__ hW,
                                  float* __restrict__ dsum, float* __restrict__ agg,
                                  int E, int N)
{
    int t = blockIdx.x * blockDim.x + threadIdx.x;
    int e = t >> 3;
    if (e >= E) return;
    int g = t & 7;
    int s = src[e], d = dst[e], r = rel[e];
    float v = att_s[(size_t)r * N + s] + att_d[(size_t)r * N + d];
    v = (v > 0.f) ? v : 0.2f * v;
    float x = __expf(v);

    uint4 raw = *(const uint4*)&hW[((size_t)r * N + s) * 64 + g * 8];
    __half2* hp = (__half2*)&raw;
    float2 f0 = __half22float2(hp[0]);
    float2 f1 = __half22float2(hp[1]);
    float2 f2 = __half22float2(hp[2]);
    float2 f3 = __half22float2(hp[3]);

    float* base = &agg[(size_t)d * 64 + g * 8];
    red_add_v4(base,     make_float4(x * f0.x, x * f0.y, x * f1.x, x * f1.y));
    red_add_v4(base + 4, make_float4(x * f2.x, x * f2.y, x * f3.x, x * f3.y));
    if (g == 0) atomicAdd(&dsum[d], x);
}

__global__ void norm_elu_seg_kernel(const float* __restrict__ agg, const float* __restrict__ dsum,
                                    const int* __restrict__ seg, float* __restrict__ feat, int n)
{
    int t = blockIdx.x * blockDim.x + threadIdx.x;
    int i = t >> 5;
    if (i >= n) return;
    int g = (t & 31) * 2;
    float s = dsum[i];
    float inv = 1.f / (s + 1e-9f);
    float2 v = *(const float2*)&agg[(size_t)i * 64 + g];
    v.x *= inv; v.y *= inv;
    v.x = (v.x > 0.f) ? v.x : expm1f(v.x);
    v.y = (v.y > 0.f) ? v.y : expm1f(v.y);
    red_add_v2(&feat[(size_t)seg[i] * 128 + g], v);
}

__global__ void segsum_kernel(const float* __restrict__ x, const int* __restrict__ seg,
                              float* __restrict__ out, int n, int ostride, int ooff)
{
    int t = blockIdx.x * blockDim.x + threadIdx.x;
    int i = t >> 4;
    if (i >= n) return;
    int g = (t & 15) * 4;
    int s = seg[i];
    float4 v = *(const float4*)&x[(size_t)i * 64 + g];
    red_add_v4(&out[(size_t)s * ostride + ooff + g], v);
}

// ---------------- MLP head ----------------
__global__ void fc1_kernel(const float* __restrict__ feat, const float* __restrict__ w,
                           const float* __restrict__ b, const float* __restrict__ prelu,
                           float* __restrict__ out)
{
    const int r0 = blockIdx.x * 16;
    const int c0 = blockIdx.y * 128;
    __shared__ float fs[16][128];
    #pragma unroll
    for (int it = 0; it < 4; it++) {
        int idx4 = it * 128 + threadIdx.x;
        int row = idx4 >> 5, col = (idx4 & 31) * 4;
        *(float4*)&fs[row][col] = *(const float4*)&feat[(size_t)(r0 + row) * 128 + col];
    }
    __syncthreads();
    const int col = c0 + threadIdx.x;
    float acc[16];
    #pragma unroll
    for (int j = 0; j < 16; j++) acc[j] = 0.f;
    #pragma unroll 4
    for (int k = 0; k < 128; k++) {
        float wv = w[k * 512 + col];
        #pragma unroll
        for (int j = 0; j < 16; j++) acc[j] += fs[j][k] * wv;
    }
    float bb = b[col], p = prelu[0];
    #pragma unroll
    for (int j = 0; j < 16; j++) {
        float v = acc[j] + bb;
        out[(size_t)(r0 + j) * 512 + col] = (v > 0.f) ? v : p * v;
    }
}

__global__ void fc2_kernel(const float* __restrict__ hid, const float* __restrict__ w,
                           const float* __restrict__ b, float* __restrict__ out)
{
    const int r0 = blockIdx.x * 16;
    const int c0 = blockIdx.y * 128;
    __shared__ float hs[16][512];
    #pragma unroll
    for (int it = 0; it < 16; it++) {
        int idx4 = it * 128 + threadIdx.x;
        int row = idx4 >> 7, col = (idx4 & 127) * 4;
        *(float4*)&hs[row][col] = *(const float4*)&hid[(size_t)(r0 + row) * 512 + col];
    }
    __syncthreads();
    const int col = c0 + threadIdx.x;
    if (col >= DO) return;
    float acc[16];
    #pragma unroll
    for (int j = 0; j < 16; j++) acc[j] = 0.f;
    #pragma unroll 4
    for (int k = 0; k < 512; k++) {
        float wv = w[k * DO + col];
        #pragma unroll
        for (int j = 0; j < 16; j++) acc[j] += hs[j][k] * wv;
    }
    float bb = b[col];
    #pragma unroll
    for (int j = 0; j < 16; j++)
        out[(size_t)(r0 + j) * DO + col] = acc[j] + bb;
}

// ---------------- launch ----------------
static inline int cdiv(int a, int b) { return (a + b - 1) / b; }

extern "C" void kernel_launch(void* const* d_in, const int* in_sizes, int n_in,
                              void* d_out, int out_size)
{
    const float* node_feats = (const float*)d_in[0];
    const int*   edge_src   = (const int*)  d_in[1];
    const int*   edge_dst   = (const int*)  d_in[2];
    const int*   edge_rel   = (const int*)  d_in[3];
    const int*   node2mol   = (const int*)  d_in[4];
    const int*   rxn_src    = (const int*)  d_in[5];
    const int*   rxn_dst    = (const int*)  d_in[6];
    const int*   rxn_rel    = (const int*)  d_in[7];
    const int*   mol2rxn    = (const int*)  d_in[8];
    const float* W1    = (const float*)d_in[9];
    const float* as1   = (const float*)d_in[10];
    const float* ad1   = (const float*)d_in[11];
    const float* W2    = (const float*)d_in[12];
    const float* as2   = (const float*)d_in[13];
    const float* ad2   = (const float*)d_in[14];
    const float* Wr    = (const float*)d_in[15];
    const float* asr   = (const float*)d_in[16];
    const float* adr   = (const float*)d_in[17];
    const float* w_fc1 = (const float*)d_in[18];
    const float* b_fc1 = (const float*)d_in[19];
    const float* prelu = (const float*)d_in[20];
    const float* w_fc2 = (const float*)d_in[21];
    const float* b_fc2 = (const float*)d_in[22];
    float* out = (float*)d_out;

    __half* p_hW;
    float *p_h1, *p_atts, *p_attd, *p_sum, *p_mol, *p_molr, *p_feat, *p_hid;
    int *p_deg, *p_rowptr, *p_cursor, *p_bsum, *p_boff;
    uint32_t* p_epk;
    cudaGetSymbolAddress((void**)&p_hW,    g_hW);
    cudaGetSymbolAddress((void**)&p_h1,    g_h1);
    cudaGetSymbolAddress((void**)&p_atts,  g_atts);
    cudaGetSymbolAddress((void**)&p_attd,  g_attd);
    cudaGetSymbolAddress((void**)&p_sum,   g_sum);
    cudaGetSymbolAddress((void**)&p_deg,   g_deg);
    cudaGetSymbolAddress((void**)&p_rowptr,g_rowptr);
    cudaGetSymbolAddress((void**)&p_cursor,g_cursor);
    cudaGetSymbolAddress((void**)&p_bsum,  g_bsum);
    cudaGetSymbolAddress((void**)&p_boff,  g_boff);
    cudaGetSymbolAddress((void**)&p_epk,   g_epk);
    cudaGetSymbolAddress((void**)&p_mol,   g_mol);
    cudaGetSymbolAddress((void**)&p_molr,  g_molr);
    cudaGetSymbolAddress((void**)&p_feat,  g_feat);
    cudaGetSymbolAddress((void**)&p_hid,   g_hid);

    const int TB = 256;
    const int NBLK = cdiv(NN, 1024);   // 98

    // ===== build atom CSR =====
    filli_kernel<<<cdiv(NN, TB), TB>>>(p_deg, 0, NN);
    hist_kernel<<<cdiv(NE, TB), TB>>>(edge_dst, p_deg, NE);
    scan_bsum_kernel<<<NBLK, 256>>>(p_deg, p_bsum, NN);
    scan_sums_kernel<<<1, 128>>>(p_bsum, p_boff, NBLK);
    scan_final_kernel<<<NBLK, 256>>>(p_deg, p_boff, p_rowptr, p_cursor, NN, NBLK);
    scatter_kernel<<<cdiv(NE, TB), TB>>>(edge_src, edge_dst, edge_rel, p_cursor, p_epk, NE);

    // ===== atom layer 1 =====
    hw_mma_kernel<<<cdiv(NN, 128), 128>>>(node_feats, W1, as1, ad1, p_hW, p_atts, p_attd, NN, RM);
    edge_agg_kernel<false><<<cdiv(NN * 32, TB), TB>>>(p_rowptr, p_epk, p_atts, p_attd, p_hW,
                                                      (const int*)0, p_h1, NN, RM);

    // ===== atom layer 2 (reduces straight into mol) =====
    fill4_kernel<<<cdiv(NM * 16, TB), TB>>>((float4*)p_mol, NM * 16);
    hw_mma_kernel<<<cdiv(NN, 128), 128>>>(p_h1, W2, as2, ad2, p_hW, p_atts, p_attd, NN, RM);
    edge_agg_kernel<true><<<cdiv(NN * 32, TB), TB>>>(p_rowptr, p_epk, p_atts, p_attd, p_hW,
                                                     node2mol, p_mol, NN, RM);

    // ===== reaction-level RGAT =====
    fill_kernel<<<cdiv(NM, TB), TB>>>(p_sum, 0.f, NM);
    fill4_kernel<<<cdiv(NM * 16, TB), TB>>>((float4*)p_molr, NM * 16);
    fill4_kernel<<<cdiv(NB * 32, TB), TB>>>((float4*)p_feat, NB * 32);
    hw_mma_kernel<<<cdiv(NM, 128), 128>>>(p_mol, Wr, asr, adr, p_hW, p_atts, p_attd, NM, RR);
    edge_fused_kernel<<<cdiv(NRE * 8, TB), TB>>>(rxn_src, rxn_dst, rxn_rel,
                                                 p_atts, p_attd, p_hW, p_sum, p_molr, NRE, NM);
    norm_elu_seg_kernel<<<cdiv(NM * 32, TB), TB>>>(p_molr, p_sum, mol2rxn, p_feat, NM);

    // ===== reaction readout (second half: direct mol sums) =====
    segsum_kernel<<<cdiv(NM * 16, TB), TB>>>(p_mol, mol2rxn, p_feat, NM, 128, 64);

    // ===== MLP head =====
    fc1_kernel<<<dim3(NB / 16, 4), 128>>>(p_feat, w_fc1, b_fc1, prelu, p_hid);
    fc2_kernel<<<dim3(NB / 16, 6), 128>>>(p_hid, w_fc2, b_fc2, out);
}

// round 12
// speedup vs baseline: 1.0510x; 1.0169x over previous
#include <cuda_runtime.h>
#include <cuda_fp16.h>
#include <math.h>
#include <stdint.h>

// ---------------- problem constants ----------------
#define NN      100000
#define NE      800000
#define DD      64
#define RM      8
#define NM      5000
#define NRE     40000
#define RR      4
#define NB      1024
#define DH      512
#define DO      703

// ---------------- scratch ----------------
__device__ __half g_hW [(size_t)RM * NN * DD];   // 102.4 MB fp16
__device__ __half g_h1 [(size_t)NN * DD];        // fp16 (consumers convert anyway)
__device__ float g_atts[(size_t)RM * NN];
__device__ float g_attd[(size_t)RM * NN];
__device__ float g_sum [NM];
__device__ int   g_deg   [NN];
__device__ int   g_rowptr[NN + 1];
__device__ int   g_cursor[NN];
__device__ int   g_bsum[128];
__device__ int   g_boff[130];
__device__ uint32_t g_epk[NE];
__device__ float g_mol [(size_t)NM * DD];
__device__ float g_molr[(size_t)NM * DD];
__device__ float g_feat[(size_t)NB * 2 * DD];
__device__ float g_hid [(size_t)NB * DH];

__device__ __forceinline__ void red_add_v4(float* p, float4 v) {
    asm volatile("red.global.add.v4.f32 [%0], {%1,%2,%3,%4};"
                 :: "l"(p), "f"(v.x), "f"(v.y), "f"(v.z), "f"(v.w) : "memory");
}
__device__ __forceinline__ void red_add_v2(float* p, float2 v) {
    asm volatile("red.global.add.v2.f32 [%0], {%1,%2};"
                 :: "l"(p), "f"(v.x), "f"(v.y) : "memory");
}

__global__ void filli_kernel(int* __restrict__ p, int v, int n) {
    int i = blockIdx.x * blockDim.x + threadIdx.x;
    if (i < n) p[i] = v;
}

// one kernel zeroes mol, molr, feat (float4) and sum (float)
#define Z_MOL4   (NM * 16)
#define Z_MOLR4  (NM * 16)
#define Z_FEAT4  (NB * 32)
__global__ void fill_all_kernel(float4* __restrict__ mol, float4* __restrict__ molr,
                                float4* __restrict__ feat, float* __restrict__ sum)
{
    int i = blockIdx.x * blockDim.x + threadIdx.x;
    float4 z = make_float4(0.f, 0.f, 0.f, 0.f);
    if (i < Z_MOL4) mol[i] = z;
    if (i < Z_MOLR4) molr[i] = z;
    if (i < Z_FEAT4) feat[i] = z;
    if (i < NM) sum[i] = 0.f;
}

// ================= CSR build =================
__global__ void hist_kernel(const int* __restrict__ dst, int* __restrict__ deg, int E) {
    int e = blockIdx.x * blockDim.x + threadIdx.x;
    if (e < E) atomicAdd(&deg[dst[e]], 1);
}

__global__ void scan_bsum_kernel(const int* __restrict__ deg, int* __restrict__ bsum, int N) {
    int b = blockIdx.x, t = threadIdx.x;
    int base = b * 1024 + t;
    int s = 0;
    #pragma unroll
    for (int q = 0; q < 4; q++) { int i = base + q * 256; if (i < N) s += deg[i]; }
    #pragma unroll
    for (int o = 16; o; o >>= 1) s += __shfl_xor_sync(0xffffffffu, s, o);
    __shared__ int ws[8];
    if ((t & 31) == 0) ws[t >> 5] = s;
    __syncthreads();
    if (t == 0) { int tot = 0; for (int i = 0; i < 8; i++) tot += ws[i]; bsum[b] = tot; }
}

__global__ void scan_sums_kernel(const int* __restrict__ bsum, int* __restrict__ boff, int nb) {
    int t = threadIdx.x, lane = t & 31, w = t >> 5;
    int v = (t < nb) ? bsum[t] : 0;
    int inc = v;
    #pragma unroll
    for (int o = 1; o < 32; o <<= 1) {
        int nv = __shfl_up_sync(0xffffffffu, inc, o);
        if (lane >= o) inc += nv;
    }
    __shared__ int ws[4];
    if (lane == 31) ws[w] = inc;
    __syncthreads();
    int add = 0;
    for (int i = 0; i < w; i++) add += ws[i];
    if (t < nb) boff[t] = add + inc - v;
    if (t == 0) boff[nb] = ws[0] + ws[1] + ws[2] + ws[3];
}

__global__ void scan_final_kernel(const int* __restrict__ deg, const int* __restrict__ boff,
                                  int* __restrict__ rowptr, int* __restrict__ cursor, int N, int nb) {
    int b = blockIdx.x, t = threadIdx.x, lane = t & 31, wid = t >> 5;
    int idx0 = b * 1024 + t * 4;
    int v0 = 0, v1 = 0, v2 = 0, v3 = 0;
    if (idx0 + 0 < N) v0 = deg[idx0 + 0];
    if (idx0 + 1 < N) v1 = deg[idx0 + 1];
    if (idx0 + 2 < N) v2 = deg[idx0 + 2];
    if (idx0 + 3 < N) v3 = deg[idx0 + 3];
    int tot = v0 + v1 + v2 + v3;
    int inc = tot;
    #pragma unroll
    for (int o = 1; o < 32; o <<= 1) {
        int nv = __shfl_up_sync(0xffffffffu, inc, o);
        if (lane >= o) inc += nv;
    }
    __shared__ int wsum[8], woff[8];
    if (lane == 31) wsum[wid] = inc;
    __syncthreads();
    if (t == 0) { int a = 0; for (int i = 0; i < 8; i++) { woff[i] = a; a += wsum[i]; } }
    __syncthreads();
    int run = boff[b] + woff[wid] + inc - tot;
    if (idx0 + 0 < N) { rowptr[idx0 + 0] = run; cursor[idx0 + 0] = run; } run += v0;
    if (idx0 + 1 < N) { rowptr[idx0 + 1] = run; cursor[idx0 + 1] = run; } run += v1;
    if (idx0 + 2 < N) { rowptr[idx0 + 2] = run; cursor[idx0 + 2] = run; } run += v2;
    if (idx0 + 3 < N) { rowptr[idx0 + 3] = run; cursor[idx0 + 3] = run; }
    if (b == 0 && t == 0) rowptr[N] = boff[nb];
}

__global__ void scatter_kernel(const int* __restrict__ src, const int* __restrict__ dst,
                               const int* __restrict__ rel,
                               int* __restrict__ cursor, uint32_t* __restrict__ epk, int E) {
    int e = blockIdx.x * blockDim.x + threadIdx.x;
    if (e >= E) return;
    int pos = atomicAdd(&cursor[dst[e]], 1);
    epk[pos] = (uint32_t)src[e] | ((uint32_t)rel[e] << 20);
}

// ================= warp-MMA helpers =================
__device__ __forceinline__ uint32_t smem_u32(const void* p) {
    return (uint32_t)__cvta_generic_to_shared(p);
}
#define LDSM_X4(r0, r1, r2, r3, addr) \
    asm volatile("ldmatrix.sync.aligned.m8n8.x4.shared.b16 {%0,%1,%2,%3}, [%4];" \
                 : "=r"(r0), "=r"(r1), "=r"(r2), "=r"(r3) : "r"(addr))
#define LDSM_X2T(r0, r1, addr) \
    asm volatile("ldmatrix.sync.aligned.m8n8.x2.trans.shared.b16 {%0,%1}, [%2];" \
                 : "=r"(r0), "=r"(r1) : "r"(addr))
#define MMA16816(c, a, b) \
    asm volatile("mma.sync.aligned.m16n8k16.row.col.f32.f16.f16.f32 " \
                 "{%0,%1,%2,%3}, {%4,%5,%6,%7}, {%8,%9}, {%0,%1,%2,%3};" \
                 : "+f"((c)[0]), "+f"((c)[1]), "+f"((c)[2]), "+f"((c)[3]) \
                 : "r"((a)[0]), "r"((a)[1]), "r"((a)[2]), "r"((a)[3]), \
                   "r"((b)[0]), "r"((b)[1]))

// ---------------- hW GEMM on HMMA + fused attention-logit epilogue ----------------
// Double-buffered W tile in smem; h-tile smem reused as output staging
// (warp-private rows), smem 40 KB. Templated on input dtype.
template<typename TIN>
__global__ __launch_bounds__(128)
void hw_mma_kernel(const TIN* __restrict__ h,
                   const float* __restrict__ W,
                   const float* __restrict__ a_src,
                   const float* __restrict__ a_dst,
                   __half* __restrict__ hW,
                   float* __restrict__ att_s,
                   float* __restrict__ att_d,
                   int N, int R)
{
    __shared__ __align__(16) __half sa [128 * 72];   // h tile, then output staging
    __shared__ __align__(16) __half swt[2][64 * 72];
    __shared__ float sas[8 * 64], sad[8 * 64];

    const int tid  = threadIdx.x;
    const int wid  = tid >> 5;
    const int lane = tid & 31;
    const int n0   = blockIdx.x * 128;

    for (int i = tid; i < R * 64; i += 128) { sas[i] = a_src[i]; sad[i] = a_dst[i]; }

    // h tile -> fp16, stride 72
    #pragma unroll
    for (int it = 0; it < 8; it++) {
        int chunk = it * 128 + tid;
        int row = chunk >> 3;
        int c8  = (chunk & 7) * 8;
        int n = n0 + row;
        if (sizeof(TIN) == 4) {
            float4 a = make_float4(0.f,0.f,0.f,0.f), b = a;
            if (n < N) {
                a = *(const float4*)((const float*)h + (size_t)n * 64 + c8);
                b = *(const float4*)((const float*)h + (size_t)n * 64 + c8 + 4);
            }
            __half2 pk[4];
            pk[0] = __floats2half2_rn(a.x, a.y);
            pk[1] = __floats2half2_rn(a.z, a.w);
            pk[2] = __floats2half2_rn(b.x, b.y);
            pk[3] = __floats2half2_rn(b.z, b.w);
            *(uint4*)&sa[row * 72 + c8] = *(uint4*)pk;
        } else {
            uint4 v = make_uint4(0u, 0u, 0u, 0u);
            if (n < N) v = *(const uint4*)((const __half*)h + (size_t)n * 64 + c8);
            *(uint4*)&sa[row * 72 + c8] = v;
        }
    }

    // preload W_0 into swt[0]
    {
        const float4* Wr4 = (const float4*)W;
        #pragma unroll
        for (int it = 0; it < 8; it++) {
            int i = it * 128 + tid;
            float4 f = Wr4[i];
            int k = i >> 4, c = (i & 15) * 4;
            *(__half2*)&swt[0][k * 72 + c]     = __floats2half2_rn(f.x, f.y);
            *(__half2*)&swt[0][k * 72 + c + 2] = __floats2half2_rn(f.z, f.w);
        }
    }
    __syncthreads();

    // A fragments, held across relations (warp reads only its own 32 rows)
    uint32_t afrag[2][4][4];
    {
        const int l15 = lane & 15;
        const int lhi = lane >> 4;
        #pragma unroll
        for (int mt = 0; mt < 2; mt++)
            #pragma unroll
            for (int kk = 0; kk < 4; kk++) {
                uint32_t addr = smem_u32(&sa[(wid * 32 + mt * 16 + l15) * 72 + kk * 16 + lhi * 8]);
                LDSM_X4(afrag[mt][kk][0], afrag[mt][kk][1],
                        afrag[mt][kk][2], afrag[mt][kk][3], addr);
            }
    }
    // sa rows are now dead; each warp reuses ITS OWN 32 rows as staging.

    const int t4 = lane >> 2;
    const int t2 = (lane & 3) * 2;

    for (int r = 0; r < R; r++) {
        const int buf = r & 1;

        float c[2][8][4];
        #pragma unroll
        for (int mt = 0; mt < 2; mt++)
            #pragma unroll
            for (int j = 0; j < 8; j++)
                #pragma unroll
                for (int q = 0; q < 4; q++) c[mt][j][q] = 0.f;

        #pragma unroll
        for (int kk = 0; kk < 4; kk++) {
            uint32_t b[8][2];
            const int l15 = lane & 15;
            #pragma unroll
            for (int j = 0; j < 8; j++) {
                uint32_t addr = smem_u32(&swt[buf][(kk * 16 + l15) * 72 + j * 8]);
                LDSM_X2T(b[j][0], b[j][1], addr);
            }
            #pragma unroll
            for (int mt = 0; mt < 2; mt++)
                #pragma unroll
                for (int j = 0; j < 8; j++)
                    MMA16816(c[mt][j], afrag[mt][kk], b[j]);
        }

        // convert next relation's W into the other buffer (overlaps epilogue)
        if (r + 1 < R) {
            const float4* Wr4 = (const float4*)(W + (size_t)(r + 1) * 4096);
            #pragma unroll
            for (int it = 0; it < 8; it++) {
                int i = it * 128 + tid;
                float4 f = Wr4[i];
                int k = i >> 4, cc = (i & 15) * 4;
                *(__half2*)&swt[1 - buf][k * 72 + cc]     = __floats2half2_rn(f.x, f.y);
                *(__half2*)&swt[1 - buf][k * 72 + cc + 2] = __floats2half2_rn(f.z, f.w);
            }
        }

        // ---- fused attention logits ----
        #pragma unroll
        for (int mt = 0; mt < 2; mt++) {
            float ps0 = 0.f, pd0 = 0.f, ps1 = 0.f, pd1 = 0.f;
            #pragma unroll
            for (int j = 0; j < 8; j++) {
                float as0 = sas[r * 64 + j * 8 + t2], as1 = sas[r * 64 + j * 8 + t2 + 1];
                float ad0 = sad[r * 64 + j * 8 + t2], ad1 = sad[r * 64 + j * 8 + t2 + 1];
                ps0 += c[mt][j][0] * as0 + c[mt][j][1] * as1;
                pd0 += c[mt][j][0] * ad0 + c[mt][j][1] * ad1;
                ps1 += c[mt][j][2] * as0 + c[mt][j][3] * as1;
                pd1 += c[mt][j][2] * ad0 + c[mt][j][3] * ad1;
            }
            #pragma unroll
            for (int o = 1; o <= 2; o <<= 1) {
                ps0 += __shfl_xor_sync(0xffffffffu, ps0, o);
                pd0 += __shfl_xor_sync(0xffffffffu, pd0, o);
                ps1 += __shfl_xor_sync(0xffffffffu, ps1, o);
                pd1 += __shfl_xor_sync(0xffffffffu, pd1, o);
            }
            if ((lane & 3) == 0) {
                int n1 = n0 + wid * 32 + mt * 16 + t4;
                int n2 = n1 + 8;
                if (n1 < N) { att_s[(size_t)r * N + n1] = ps0; att_d[(size_t)r * N + n1] = pd0; }
                if (n2 < N) { att_s[(size_t)r * N + n2] = ps1; att_d[(size_t)r * N + n2] = pd1; }
            }
        }

        // ---- warp-private staging (own 32 rows of sa) + coalesced store ----
        #pragma unroll
        for (int mt = 0; mt < 2; mt++) {
            int rr = wid * 32 + mt * 16 + t4;
            #pragma unroll
            for (int j = 0; j < 8; j++) {
                *(__half2*)&sa[rr * 72 + j * 8 + t2]       = __floats2half2_rn(c[mt][j][0], c[mt][j][1]);
                *(__half2*)&sa[(rr + 8) * 72 + j * 8 + t2] = __floats2half2_rn(c[mt][j][2], c[mt][j][3]);
            }
        }
        __syncwarp();
        #pragma unroll
        for (int it = 0; it < 8; it++) {
            int idx = it * 32 + lane;
            int rowl = idx >> 3;
            int q    = idx & 7;
            int row  = wid * 32 + rowl;
            int n = n0 + row;
            if (n < N)
                *(uint4*)&hW[((size_t)r * N + n) * 64 + q * 8] = *(uint4*)&sa[row * 72 + q * 8];
        }
        __syncthreads();   // next W buffer ready
    }
}

// ---------------- CSR edge aggregation: one warp per dst, 4-edge unroll ----------------
// SEG=false: writes fp16 rows to outh (h1). SEG=true: red-adds fp32 into mol.
template<bool SEG>
__global__ void edge_agg_kernel(const int* __restrict__ rowptr, const uint32_t* __restrict__ epk,
                                const float* __restrict__ att_s, const float* __restrict__ att_d,
                                const __half* __restrict__ hW, const int* __restrict__ seg,
                                void* __restrict__ outh, int N, int R)
{
    int w = (blockIdx.x * blockDim.x + threadIdx.x) >> 5;
    int lane = threadIdx.x & 31;
    if (w >= N) return;
    int beg = rowptr[w], end = rowptr[w + 1];
    float adv = (lane < R) ? att_d[(size_t)lane * N + w] : 0.f;
    float acc0 = 0.f, acc1 = 0.f, ssum = 0.f;
    int e = beg;
    for (; e + 3 < end; e += 4) {
        uint32_t p0 = epk[e], p1 = epk[e + 1], p2 = epk[e + 2], p3 = epk[e + 3];
        int s0 = p0 & 0xFFFFF, r0 = p0 >> 20;
        int s1 = p1 & 0xFFFFF, r1 = p1 >> 20;
        int s2 = p2 & 0xFFFFF, r2 = p2 >> 20;
        int s3 = p3 & 0xFFFFF, r3 = p3 >> 20;
        float sc0 = att_s[(size_t)r0 * N + s0] + __shfl_sync(0xffffffffu, adv, r0);
        float sc1 = att_s[(size_t)r1 * N + s1] + __shfl_sync(0xffffffffu, adv, r1);
        float sc2 = att_s[(size_t)r2 * N + s2] + __shfl_sync(0xffffffffu, adv, r2);
        float sc3 = att_s[(size_t)r3 * N + s3] + __shfl_sync(0xffffffffu, adv, r3);
        sc0 = (sc0 > 0.f) ? sc0 : 0.2f * sc0;
        sc1 = (sc1 > 0.f) ? sc1 : 0.2f * sc1;
        sc2 = (sc2 > 0.f) ? sc2 : 0.2f * sc2;
        sc3 = (sc3 > 0.f) ? sc3 : 0.2f * sc3;
        float x0 = __expf(sc0), x1 = __expf(sc1), x2 = __expf(sc2), x3 = __expf(sc3);
        __half2 h0 = *(const __half2*)&hW[((size_t)r0 * N + s0) * 64 + lane * 2];
        __half2 h1 = *(const __half2*)&hW[((size_t)r1 * N + s1) * 64 + lane * 2];
        __half2 h2 = *(const __half2*)&hW[((size_t)r2 * N + s2) * 64 + lane * 2];
        __half2 h3 = *(const __half2*)&hW[((size_t)r3 * N + s3) * 64 + lane * 2];
        float2 f0 = __half22float2(h0), f1 = __half22float2(h1);
        float2 f2 = __half22float2(h2), f3 = __half22float2(h3);
        acc0 = fmaf(x0, f0.x, acc0); acc1 = fmaf(x0, f0.y, acc1);
        acc0 = fmaf(x1, f1.x, acc0); acc1 = fmaf(x1, f1.y, acc1);
        acc0 = fmaf(x2, f2.x, acc0); acc1 = fmaf(x2, f2.y, acc1);
        acc0 = fmaf(x3, f3.x, acc0); acc1 = fmaf(x3, f3.y, acc1);
        ssum += (x0 + x1) + (x2 + x3);
    }
    for (; e < end; e++) {
        uint32_t p0 = epk[e];
        int s0 = p0 & 0xFFFFF, r0 = p0 >> 20;
        float sc0 = att_s[(size_t)r0 * N + s0] + __shfl_sync(0xffffffffu, adv, r0);
        sc0 = (sc0 > 0.f) ? sc0 : 0.2f * sc0;
        float x0 = __expf(sc0);
        __half2 h0 = *(const __half2*)&hW[((size_t)r0 * N + s0) * 64 + lane * 2];
        float2 f0 = __half22float2(h0);
        acc0 = fmaf(x0, f0.x, acc0); acc1 = fmaf(x0, f0.y, acc1);
        ssum += x0;
    }
    float inv = 1.f / (ssum + 1e-9f);
    float v0 = acc0 * inv, v1 = acc1 * inv;
    v0 = (v0 > 0.f) ? v0 : expm1f(v0);
    v1 = (v1 > 0.f) ? v1 : expm1f(v1);
    if (SEG) {
        red_add_v2((float*)outh + (size_t)seg[w] * 64 + lane * 2, make_float2(v0, v1));
    } else {
        *(__half2*)((__half*)outh + (size_t)w * 64 + lane * 2) = __floats2half2_rn(v0, v1);
    }
}

// ---------------- atomic edge path (reaction graph only) ----------------
__global__ void edge_fused_kernel(const int* __restrict__ src, const int* __restrict__ dst,
                                  const int* __restrict__ rel,
                                  const float* __restrict__ att_s, const float* __restrict__ att_d,
                                  const __half* __restrict__ hW,
                                  float* __restrict__ dsum, float* __restrict__ agg,
                                  int E, int N)
{
    int t = blockIdx.x * blockDim.x + threadIdx.x;
    int e = t >> 3;
    if (e >= E) return;
    int g = t & 7;
    int s = src[e], d = dst[e], r = rel[e];
    float v = att_s[(size_t)r * N + s] + att_d[(size_t)r * N + d];
    v = (v > 0.f) ? v : 0.2f * v;
    float x = __expf(v);

    uint4 raw = *(const uint4*)&hW[((size_t)r * N + s) * 64 + g * 8];
    __half2* hp = (__half2*)&raw;
    float2 f0 = __half22float2(hp[0]);
    float2 f1 = __half22float2(hp[1]);
    float2 f2 = __half22float2(hp[2]);
    float2 f3 = __half22float2(hp[3]);

    float* base = &agg[(size_t)d * 64 + g * 8];
    red_add_v4(base,     make_float4(x * f0.x, x * f0.y, x * f1.x, x * f1.y));
    red_add_v4(base + 4, make_float4(x * f2.x, x * f2.y, x * f3.x, x * f3.y));
    if (g == 0) atomicAdd(&dsum[d], x);
}

__global__ void norm_elu_seg_kernel(const float* __restrict__ agg, const float* __restrict__ dsum,
                                    const int* __restrict__ seg, float* __restrict__ feat, int n)
{
    int t = blockIdx.x * blockDim.x + threadIdx.x;
    int i = t >> 5;
    if (i >= n) return;
    int g = (t & 31) * 2;
    float s = dsum[i];
    float inv = 1.f / (s + 1e-9f);
    float2 v = *(const float2*)&agg[(size_t)i * 64 + g];
    v.x *= inv; v.y *= inv;
    v.x = (v.x > 0.f) ? v.x : expm1f(v.x);
    v.y = (v.y > 0.f) ? v.y : expm1f(v.y);
    red_add_v2(&feat[(size_t)seg[i] * 128 + g], v);
}

__global__ void segsum_kernel(const float* __restrict__ x, const int* __restrict__ seg,
                              float* __restrict__ out, int n, int ostride, int ooff)
{
    int t = blockIdx.x * blockDim.x + threadIdx.x;
    int i = t >> 4;
    if (i >= n) return;
    int g = (t & 15) * 4;
    int s = seg[i];
    float4 v = *(const float4*)&x[(size_t)i * 64 + g];
    red_add_v4(&out[(size_t)s * ostride + ooff + g], v);
}

// ---------------- MLP head ----------------
__global__ void fc1_kernel(const float* __restrict__ feat, const float* __restrict__ w,
                           const float* __restrict__ b, const float* __restrict__ prelu,
                           float* __restrict__ out)
{
    const int r0 = blockIdx.x * 16;
    const int c0 = blockIdx.y * 128;
    __shared__ float fs[16][128];
    #pragma unroll
    for (int it = 0; it < 4; it++) {
        int idx4 = it * 128 + threadIdx.x;
        int row = idx4 >> 5, col = (idx4 & 31) * 4;
        *(float4*)&fs[row][col] = *(const float4*)&feat[(size_t)(r0 + row) * 128 + col];
    }
    __syncthreads();
    const int col = c0 + threadIdx.x;
    float acc[16];
    #pragma unroll
    for (int j = 0; j < 16; j++) acc[j] = 0.f;
    #pragma unroll 4
    for (int k = 0; k < 128; k++) {
        float wv = w[k * 512 + col];
        #pragma unroll
        for (int j = 0; j < 16; j++) acc[j] += fs[j][k] * wv;
    }
    float bb = b[col], p = prelu[0];
    #pragma unroll
    for (int j = 0; j < 16; j++) {
        float v = acc[j] + bb;
        out[(size_t)(r0 + j) * 512 + col] = (v > 0.f) ? v : p * v;
    }
}

__global__ void fc2_kernel(const float* __restrict__ hid, const float* __restrict__ w,
                           const float* __restrict__ b, float* __restrict__ out)
{
    const int r0 = blockIdx.x * 16;
    const int c0 = blockIdx.y * 128;
    __shared__ float hs[16][512];
    #pragma unroll
    for (int it = 0; it < 16; it++) {
        int idx4 = it * 128 + threadIdx.x;
        int row = idx4 >> 7, col = (idx4 & 127) * 4;
        *(float4*)&hs[row][col] = *(const float4*)&hid[(size_t)(r0 + row) * 512 + col];
    }
    __syncthreads();
    const int col = c0 + threadIdx.x;
    if (col >= DO) return;
    float acc[16];
    #pragma unroll
    for (int j = 0; j < 16; j++) acc[j] = 0.f;
    #pragma unroll 4
    for (int k = 0; k < 512; k++) {
        float wv = w[k * DO + col];
        #pragma unroll
        for (int j = 0; j < 16; j++) acc[j] += hs[j][k] * wv;
    }
    float bb = b[col];
    #pragma unroll
    for (int j = 0; j < 16; j++)
        out[(size_t)(r0 + j) * DO + col] = acc[j] + bb;
}

// ---------------- launch ----------------
static inline int cdiv(int a, int b) { return (a + b - 1) / b; }

extern "C" void kernel_launch(void* const* d_in, const int* in_sizes, int n_in,
                              void* d_out, int out_size)
{
    const float* node_feats = (const float*)d_in[0];
    const int*   edge_src   = (const int*)  d_in[1];
    const int*   edge_dst   = (const int*)  d_in[2];
    const int*   edge_rel   = (const int*)  d_in[3];
    const int*   node2mol   = (const int*)  d_in[4];
    const int*   rxn_src    = (const int*)  d_in[5];
    const int*   rxn_dst    = (const int*)  d_in[6];
    const int*   rxn_rel    = (const int*)  d_in[7];
    const int*   mol2rxn    = (const int*)  d_in[8];
    const float* W1    = (const float*)d_in[9];
    const float* as1   = (const float*)d_in[10];
    const float* ad1   = (const float*)d_in[11];
    const float* W2    = (const float*)d_in[12];
    const float* as2   = (const float*)d_in[13];
    const float* ad2   = (const float*)d_in[14];
    const float* Wr    = (const float*)d_in[15];
    const float* asr   = (const float*)d_in[16];
    const float* adr   = (const float*)d_in[17];
    const float* w_fc1 = (const float*)d_in[18];
    const float* b_fc1 = (const float*)d_in[19];
    const float* prelu = (const float*)d_in[20];
    const float* w_fc2 = (const float*)d_in[21];
    const float* b_fc2 = (const float*)d_in[22];
    float* out = (float*)d_out;

    __half *p_hW, *p_h1;
    float *p_atts, *p_attd, *p_sum, *p_mol, *p_molr, *p_feat, *p_hid;
    int *p_deg, *p_rowptr, *p_cursor, *p_bsum, *p_boff;
    uint32_t* p_epk;
    cudaGetSymbolAddress((void**)&p_hW,    g_hW);
    cudaGetSymbolAddress((void**)&p_h1,    g_h1);
    cudaGetSymbolAddress((void**)&p_atts,  g_atts);
    cudaGetSymbolAddress((void**)&p_attd,  g_attd);
    cudaGetSymbolAddress((void**)&p_sum,   g_sum);
    cudaGetSymbolAddress((void**)&p_deg,   g_deg);
    cudaGetSymbolAddress((void**)&p_rowptr,g_rowptr);
    cudaGetSymbolAddress((void**)&p_cursor,g_cursor);
    cudaGetSymbolAddress((void**)&p_bsum,  g_bsum);
    cudaGetSymbolAddress((void**)&p_boff,  g_boff);
    cudaGetSymbolAddress((void**)&p_epk,   g_epk);
    cudaGetSymbolAddress((void**)&p_mol,   g_mol);
    cudaGetSymbolAddress((void**)&p_molr,  g_molr);
    cudaGetSymbolAddress((void**)&p_feat,  g_feat);
    cudaGetSymbolAddress((void**)&p_hid,   g_hid);

    const int TB = 256;
    const int NBLK = cdiv(NN, 1024);   // 98

    // ===== build atom CSR + zero small buffers =====
    filli_kernel<<<cdiv(NN, TB), TB>>>(p_deg, 0, NN);
    hist_kernel<<<cdiv(NE, TB), TB>>>(edge_dst, p_deg, NE);
    scan_bsum_kernel<<<NBLK, 256>>>(p_deg, p_bsum, NN);
    scan_sums_kernel<<<1, 128>>>(p_bsum, p_boff, NBLK);
    scan_final_kernel<<<NBLK, 256>>>(p_deg, p_boff, p_rowptr, p_cursor, NN, NBLK);
    scatter_kernel<<<cdiv(NE, TB), TB>>>(edge_src, edge_dst, edge_rel, p_cursor, p_epk, NE);
    fill_all_kernel<<<cdiv(NB * 32 > NM * 16 ? NB * 32 : NM * 16, TB), TB>>>(
        (float4*)p_mol, (float4*)p_molr, (float4*)p_feat, p_sum);

    // ===== atom layer 1 =====
    hw_mma_kernel<float><<<cdiv(NN, 128), 128>>>(node_feats, W1, as1, ad1,
                                                 p_hW, p_atts, p_attd, NN, RM);
    edge_agg_kernel<false><<<cdiv(NN * 32, TB), TB>>>(p_rowptr, p_epk, p_atts, p_attd, p_hW,
                                                      (const int*)0, p_h1, NN, RM);

    // ===== atom layer 2 (reduces straight into mol) =====
    hw_mma_kernel<__half><<<cdiv(NN, 128), 128>>>(p_h1, W2, as2, ad2,
                                                  p_hW, p_atts, p_attd, NN, RM);
    edge_agg_kernel<true><<<cdiv(NN * 32, TB), TB>>>(p_rowptr, p_epk, p_atts, p_attd, p_hW,
                                                     node2mol, p_mol, NN, RM);

    // ===== reaction-level RGAT =====
    hw_mma_kernel<float><<<cdiv(NM, 128), 128>>>(p_mol, Wr, asr, adr,
                                                 p_hW, p_atts, p_attd, NM, RR);
    edge_fused_kernel<<<cdiv(NRE * 8, TB), TB>>>(rxn_src, rxn_dst, rxn_rel,
                                                 p_atts, p_attd, p_hW, p_sum, p_molr, NRE, NM);
    norm_elu_seg_kernel<<<cdiv(NM * 32, TB), TB>>>(p_molr, p_sum, mol2rxn, p_feat, NM);

    // ===== reaction readout (second half: direct mol sums) =====
    segsum_kernel<<<cdiv(NM * 16, TB), TB>>>(p_mol, mol2rxn, p_feat, NM, 128, 64);

    // ===== MLP head =====
    fc1_kernel<<<dim3(NB / 16, 4), 128>>>(p_feat, w_fc1, b_fc1, prelu, p_hid);
    fc2_kernel<<<dim3(NB / 16, 6), 128>>>(p_hid, w_fc2, b_fc2, out);
}

// round 13
// speedup vs baseline: 1.0759x; 1.0237x over previous
#include <cuda_runtime.h>
#include <cuda_fp16.h>
#include <math.h>
#include <stdint.h>

// ---------------- problem constants ----------------
#define NN      100000
#define NE      800000
#define DD      64
#define RM      8
#define NM      5000
#define NRE     40000
#define RR      4
#define NB      1024
#define DH      512
#define DO      703

// ---------------- scratch ----------------
__device__ __half g_hW [(size_t)RM * NN * DD];   // 102.4 MB fp16
__device__ __half g_h1 [(size_t)NN * DD];        // fp16
__device__ float g_atts[(size_t)RM * NN];
__device__ float g_attd[(size_t)RM * NN];
__device__ float g_sum [NM];
__device__ int   g_deg   [NN];
__device__ int   g_rowptr[NN + 1];
__device__ int   g_cursor[NN];
__device__ int   g_bsum[128];
__device__ int   g_boff[130];
__device__ uint32_t g_epk[NE];
__device__ float g_mol [(size_t)NM * DD];
__device__ float g_molr[(size_t)NM * DD];
__device__ float g_feat[(size_t)NB * 2 * DD];
__device__ float g_hid [(size_t)NB * DH];

__device__ __forceinline__ void red_add_v4(float* p, float4 v) {
    asm volatile("red.global.add.v4.f32 [%0], {%1,%2,%3,%4};"
                 :: "l"(p), "f"(v.x), "f"(v.y), "f"(v.z), "f"(v.w) : "memory");
}
__device__ __forceinline__ void red_add_v2(float* p, float2 v) {
    asm volatile("red.global.add.v2.f32 [%0], {%1,%2};"
                 :: "l"(p), "f"(v.x), "f"(v.y) : "memory");
}

__global__ void filli_kernel(int* __restrict__ p, int v, int n) {
    int i = blockIdx.x * blockDim.x + threadIdx.x;
    if (i < n) p[i] = v;
}

#define Z_MOL4   (NM * 16)
#define Z_MOLR4  (NM * 16)
#define Z_FEAT4  (NB * 32)
__global__ void fill_all_kernel(float4* __restrict__ mol, float4* __restrict__ molr,
                                float4* __restrict__ feat, float* __restrict__ sum)
{
    int i = blockIdx.x * blockDim.x + threadIdx.x;
    float4 z = make_float4(0.f, 0.f, 0.f, 0.f);
    if (i < Z_MOL4) mol[i] = z;
    if (i < Z_MOLR4) molr[i] = z;
    if (i < Z_FEAT4) feat[i] = z;
    if (i < NM) sum[i] = 0.f;
}

// ================= CSR build =================
__global__ void hist_kernel(const int* __restrict__ dst, int* __restrict__ deg, int E) {
    int e = blockIdx.x * blockDim.x + threadIdx.x;
    if (e < E) atomicAdd(&deg[dst[e]], 1);
}

__global__ void scan_bsum_kernel(const int* __restrict__ deg, int* __restrict__ bsum, int N) {
    int b = blockIdx.x, t = threadIdx.x;
    int base = b * 1024 + t;
    int s = 0;
    #pragma unroll
    for (int q = 0; q < 4; q++) { int i = base + q * 256; if (i < N) s += deg[i]; }
    #pragma unroll
    for (int o = 16; o; o >>= 1) s += __shfl_xor_sync(0xffffffffu, s, o);
    __shared__ int ws[8];
    if ((t & 31) == 0) ws[t >> 5] = s;
    __syncthreads();
    if (t == 0) { int tot = 0; for (int i = 0; i < 8; i++) tot += ws[i]; bsum[b] = tot; }
}

__global__ void scan_sums_kernel(const int* __restrict__ bsum, int* __restrict__ boff, int nb) {
    int t = threadIdx.x, lane = t & 31, w = t >> 5;
    int v = (t < nb) ? bsum[t] : 0;
    int inc = v;
    #pragma unroll
    for (int o = 1; o < 32; o <<= 1) {
        int nv = __shfl_up_sync(0xffffffffu, inc, o);
        if (lane >= o) inc += nv;
    }
    __shared__ int ws[4];
    if (lane == 31) ws[w] = inc;
    __syncthreads();
    int add = 0;
    for (int i = 0; i < w; i++) add += ws[i];
    if (t < nb) boff[t] = add + inc - v;
    if (t == 0) boff[nb] = ws[0] + ws[1] + ws[2] + ws[3];
}

__global__ void scan_final_kernel(const int* __restrict__ deg, const int* __restrict__ boff,
                                  int* __restrict__ rowptr, int* __restrict__ cursor, int N, int nb) {
    int b = blockIdx.x, t = threadIdx.x, lane = t & 31, wid = t >> 5;
    int idx0 = b * 1024 + t * 4;
    int v0 = 0, v1 = 0, v2 = 0, v3 = 0;
    if (idx0 + 0 < N) v0 = deg[idx0 + 0];
    if (idx0 + 1 < N) v1 = deg[idx0 + 1];
    if (idx0 + 2 < N) v2 = deg[idx0 + 2];
    if (idx0 + 3 < N) v3 = deg[idx0 + 3];
    int tot = v0 + v1 + v2 + v3;
    int inc = tot;
    #pragma unroll
    for (int o = 1; o < 32; o <<= 1) {
        int nv = __shfl_up_sync(0xffffffffu, inc, o);
        if (lane >= o) inc += nv;
    }
    __shared__ int wsum[8], woff[8];
    if (lane == 31) wsum[wid] = inc;
    __syncthreads();
    if (t == 0) { int a = 0; for (int i = 0; i < 8; i++) { woff[i] = a; a += wsum[i]; } }
    __syncthreads();
    int run = boff[b] + woff[wid] + inc - tot;
    if (idx0 + 0 < N) { rowptr[idx0 + 0] = run; cursor[idx0 + 0] = run; } run += v0;
    if (idx0 + 1 < N) { rowptr[idx0 + 1] = run; cursor[idx0 + 1] = run; } run += v1;
    if (idx0 + 2 < N) { rowptr[idx0 + 2] = run; cursor[idx0 + 2] = run; } run += v2;
    if (idx0 + 3 < N) { rowptr[idx0 + 3] = run; cursor[idx0 + 3] = run; }
    if (b == 0 && t == 0) rowptr[N] = boff[nb];
}

__global__ void scatter_kernel(const int* __restrict__ src, const int* __restrict__ dst,
                               const int* __restrict__ rel,
                               int* __restrict__ cursor, uint32_t* __restrict__ epk, int E) {
    int e = blockIdx.x * blockDim.x + threadIdx.x;
    if (e >= E) return;
    int pos = atomicAdd(&cursor[dst[e]], 1);
    epk[pos] = (uint32_t)src[e] | ((uint32_t)rel[e] << 20);
}

// ================= warp-MMA helpers =================
__device__ __forceinline__ uint32_t smem_u32(const void* p) {
    return (uint32_t)__cvta_generic_to_shared(p);
}
#define LDSM_X4(r0, r1, r2, r3, addr) \
    asm volatile("ldmatrix.sync.aligned.m8n8.x4.shared.b16 {%0,%1,%2,%3}, [%4];" \
                 : "=r"(r0), "=r"(r1), "=r"(r2), "=r"(r3) : "r"(addr))
#define LDSM_X2T(r0, r1, addr) \
    asm volatile("ldmatrix.sync.aligned.m8n8.x2.trans.shared.b16 {%0,%1}, [%2];" \
                 : "=r"(r0), "=r"(r1) : "r"(addr))
#define MMA16816(c, a, b) \
    asm volatile("mma.sync.aligned.m16n8k16.row.col.f32.f16.f16.f32 " \
                 "{%0,%1,%2,%3}, {%4,%5,%6,%7}, {%8,%9}, {%0,%1,%2,%3};" \
                 : "+f"((c)[0]), "+f"((c)[1]), "+f"((c)[2]), "+f"((c)[3]) \
                 : "r"((a)[0]), "r"((a)[1]), "r"((a)[2]), "r"((a)[3]), \
                   "r"((b)[0]), "r"((b)[1]))

// ---------------- hW GEMM on HMMA + fused attention-logit epilogue ----------------
template<typename TIN>
__global__ __launch_bounds__(128)
void hw_mma_kernel(const TIN* __restrict__ h,
                   const float* __restrict__ W,
                   const float* __restrict__ a_src,
                   const float* __restrict__ a_dst,
                   __half* __restrict__ hW,
                   float* __restrict__ att_s,
                   float* __restrict__ att_d,
                   int N, int R)
{
    __shared__ __align__(16) __half sa [128 * 72];   // h tile, then output staging
    __shared__ __align__(16) __half swt[2][64 * 72];
    __shared__ float sas[8 * 64], sad[8 * 64];

    const int tid  = threadIdx.x;
    const int wid  = tid >> 5;
    const int lane = tid & 31;
    const int n0   = blockIdx.x * 128;

    for (int i = tid; i < R * 64; i += 128) { sas[i] = a_src[i]; sad[i] = a_dst[i]; }

    #pragma unroll
    for (int it = 0; it < 8; it++) {
        int chunk = it * 128 + tid;
        int row = chunk >> 3;
        int c8  = (chunk & 7) * 8;
        int n = n0 + row;
        if (sizeof(TIN) == 4) {
            float4 a = make_float4(0.f,0.f,0.f,0.f), b = a;
            if (n < N) {
                a = *(const float4*)((const float*)h + (size_t)n * 64 + c8);
                b = *(const float4*)((const float*)h + (size_t)n * 64 + c8 + 4);
            }
            __half2 pk[4];
            pk[0] = __floats2half2_rn(a.x, a.y);
            pk[1] = __floats2half2_rn(a.z, a.w);
            pk[2] = __floats2half2_rn(b.x, b.y);
            pk[3] = __floats2half2_rn(b.z, b.w);
            *(uint4*)&sa[row * 72 + c8] = *(uint4*)pk;
        } else {
            uint4 v = make_uint4(0u, 0u, 0u, 0u);
            if (n < N) v = *(const uint4*)((const __half*)h + (size_t)n * 64 + c8);
            *(uint4*)&sa[row * 72 + c8] = v;
        }
    }

    {
        const float4* Wr4 = (const float4*)W;
        #pragma unroll
        for (int it = 0; it < 8; it++) {
            int i = it * 128 + tid;
            float4 f = Wr4[i];
            int k = i >> 4, c = (i & 15) * 4;
            *(__half2*)&swt[0][k * 72 + c]     = __floats2half2_rn(f.x, f.y);
            *(__half2*)&swt[0][k * 72 + c + 2] = __floats2half2_rn(f.z, f.w);
        }
    }
    __syncthreads();

    uint32_t afrag[2][4][4];
    {
        const int l15 = lane & 15;
        const int lhi = lane >> 4;
        #pragma unroll
        for (int mt = 0; mt < 2; mt++)
            #pragma unroll
            for (int kk = 0; kk < 4; kk++) {
                uint32_t addr = smem_u32(&sa[(wid * 32 + mt * 16 + l15) * 72 + kk * 16 + lhi * 8]);
                LDSM_X4(afrag[mt][kk][0], afrag[mt][kk][1],
                        afrag[mt][kk][2], afrag[mt][kk][3], addr);
            }
    }

    const int t4 = lane >> 2;
    const int t2 = (lane & 3) * 2;

    for (int r = 0; r < R; r++) {
        const int buf = r & 1;

        float c[2][8][4];
        #pragma unroll
        for (int mt = 0; mt < 2; mt++)
            #pragma unroll
            for (int j = 0; j < 8; j++)
                #pragma unroll
                for (int q = 0; q < 4; q++) c[mt][j][q] = 0.f;

        #pragma unroll
        for (int kk = 0; kk < 4; kk++) {
            uint32_t b[8][2];
            const int l15 = lane & 15;
            #pragma unroll
            for (int j = 0; j < 8; j++) {
                uint32_t addr = smem_u32(&swt[buf][(kk * 16 + l15) * 72 + j * 8]);
                LDSM_X2T(b[j][0], b[j][1], addr);
            }
            #pragma unroll
            for (int mt = 0; mt < 2; mt++)
                #pragma unroll
                for (int j = 0; j < 8; j++)
                    MMA16816(c[mt][j], afrag[mt][kk], b[j]);
        }

        if (r + 1 < R) {
            const float4* Wr4 = (const float4*)(W + (size_t)(r + 1) * 4096);
            #pragma unroll
            for (int it = 0; it < 8; it++) {
                int i = it * 128 + tid;
                float4 f = Wr4[i];
                int k = i >> 4, cc = (i & 15) * 4;
                *(__half2*)&swt[1 - buf][k * 72 + cc]     = __floats2half2_rn(f.x, f.y);
                *(__half2*)&swt[1 - buf][k * 72 + cc + 2] = __floats2half2_rn(f.z, f.w);
            }
        }

        #pragma unroll
        for (int mt = 0; mt < 2; mt++) {
            float ps0 = 0.f, pd0 = 0.f, ps1 = 0.f, pd1 = 0.f;
            #pragma unroll
            for (int j = 0; j < 8; j++) {
                float as0 = sas[r * 64 + j * 8 + t2], as1 = sas[r * 64 + j * 8 + t2 + 1];
                float ad0 = sad[r * 64 + j * 8 + t2], ad1 = sad[r * 64 + j * 8 + t2 + 1];
                ps0 += c[mt][j][0] * as0 + c[mt][j][1] * as1;
                pd0 += c[mt][j][0] * ad0 + c[mt][j][1] * ad1;
                ps1 += c[mt][j][2] * as0 + c[mt][j][3] * as1;
                pd1 += c[mt][j][2] * ad0 + c[mt][j][3] * ad1;
            }
            #pragma unroll
            for (int o = 1; o <= 2; o <<= 1) {
                ps0 += __shfl_xor_sync(0xffffffffu, ps0, o);
                pd0 += __shfl_xor_sync(0xffffffffu, pd0, o);
                ps1 += __shfl_xor_sync(0xffffffffu, ps1, o);
                pd1 += __shfl_xor_sync(0xffffffffu, pd1, o);
            }
            if ((lane & 3) == 0) {
                int n1 = n0 + wid * 32 + mt * 16 + t4;
                int n2 = n1 + 8;
                if (n1 < N) { att_s[(size_t)r * N + n1] = ps0; att_d[(size_t)r * N + n1] = pd0; }
                if (n2 < N) { att_s[(size_t)r * N + n2] = ps1; att_d[(size_t)r * N + n2] = pd1; }
            }
        }

        #pragma unroll
        for (int mt = 0; mt < 2; mt++) {
            int rr = wid * 32 + mt * 16 + t4;
            #pragma unroll
            for (int j = 0; j < 8; j++) {
                *(__half2*)&sa[rr * 72 + j * 8 + t2]       = __floats2half2_rn(c[mt][j][0], c[mt][j][1]);
                *(__half2*)&sa[(rr + 8) * 72 + j * 8 + t2] = __floats2half2_rn(c[mt][j][2], c[mt][j][3]);
            }
        }
        __syncwarp();
        #pragma unroll
        for (int it = 0; it < 8; it++) {
            int idx = it * 32 + lane;
            int rowl = idx >> 3;
            int q    = idx & 7;
            int row  = wid * 32 + rowl;
            int n = n0 + row;
            if (n < N)
                *(uint4*)&hW[((size_t)r * N + n) * 64 + q * 8] = *(uint4*)&sa[row * 72 + q * 8];
        }
        __syncthreads();
    }
}

// ---------------- CSR edge aggregation ----------------
template<bool SEG>
__global__ void edge_agg_kernel(const int* __restrict__ rowptr, const uint32_t* __restrict__ epk,
                                const float* __restrict__ att_s, const float* __restrict__ att_d,
                                const __half* __restrict__ hW, const int* __restrict__ seg,
                                void* __restrict__ outh, int N, int R)
{
    int w = (blockIdx.x * blockDim.x + threadIdx.x) >> 5;
    int lane = threadIdx.x & 31;
    if (w >= N) return;
    int beg = rowptr[w], end = rowptr[w + 1];
    float adv = (lane < R) ? att_d[(size_t)lane * N + w] : 0.f;
    float acc0 = 0.f, acc1 = 0.f, ssum = 0.f;
    int e = beg;
    for (; e + 3 < end; e += 4) {
        uint32_t p0 = epk[e], p1 = epk[e + 1], p2 = epk[e + 2], p3 = epk[e + 3];
        int s0 = p0 & 0xFFFFF, r0 = p0 >> 20;
        int s1 = p1 & 0xFFFFF, r1 = p1 >> 20;
        int s2 = p2 & 0xFFFFF, r2 = p2 >> 20;
        int s3 = p3 & 0xFFFFF, r3 = p3 >> 20;
        float sc0 = att_s[(size_t)r0 * N + s0] + __shfl_sync(0xffffffffu, adv, r0);
        float sc1 = att_s[(size_t)r1 * N + s1] + __shfl_sync(0xffffffffu, adv, r1);
        float sc2 = att_s[(size_t)r2 * N + s2] + __shfl_sync(0xffffffffu, adv, r2);
        float sc3 = att_s[(size_t)r3 * N + s3] + __shfl_sync(0xffffffffu, adv, r3);
        sc0 = (sc0 > 0.f) ? sc0 : 0.2f * sc0;
        sc1 = (sc1 > 0.f) ? sc1 : 0.2f * sc1;
        sc2 = (sc2 > 0.f) ? sc2 : 0.2f * sc2;
        sc3 = (sc3 > 0.f) ? sc3 : 0.2f * sc3;
        float x0 = __expf(sc0), x1 = __expf(sc1), x2 = __expf(sc2), x3 = __expf(sc3);
        __half2 h0 = *(const __half2*)&hW[((size_t)r0 * N + s0) * 64 + lane * 2];
        __half2 h1 = *(const __half2*)&hW[((size_t)r1 * N + s1) * 64 + lane * 2];
        __half2 h2 = *(const __half2*)&hW[((size_t)r2 * N + s2) * 64 + lane * 2];
        __half2 h3 = *(const __half2*)&hW[((size_t)r3 * N + s3) * 64 + lane * 2];
        float2 f0 = __half22float2(h0), f1 = __half22float2(h1);
        float2 f2 = __half22float2(h2), f3 = __half22float2(h3);
        acc0 = fmaf(x0, f0.x, acc0); acc1 = fmaf(x0, f0.y, acc1);
        acc0 = fmaf(x1, f1.x, acc0); acc1 = fmaf(x1, f1.y, acc1);
        acc0 = fmaf(x2, f2.x, acc0); acc1 = fmaf(x2, f2.y, acc1);
        acc0 = fmaf(x3, f3.x, acc0); acc1 = fmaf(x3, f3.y, acc1);
        ssum += (x0 + x1) + (x2 + x3);
    }
    for (; e < end; e++) {
        uint32_t p0 = epk[e];
        int s0 = p0 & 0xFFFFF, r0 = p0 >> 20;
        float sc0 = att_s[(size_t)r0 * N + s0] + __shfl_sync(0xffffffffu, adv, r0);
        sc0 = (sc0 > 0.f) ? sc0 : 0.2f * sc0;
        float x0 = __expf(sc0);
        __half2 h0 = *(const __half2*)&hW[((size_t)r0 * N + s0) * 64 + lane * 2];
        float2 f0 = __half22float2(h0);
        acc0 = fmaf(x0, f0.x, acc0); acc1 = fmaf(x0, f0.y, acc1);
        ssum += x0;
    }
    float inv = 1.f / (ssum + 1e-9f);
    float v0 = acc0 * inv, v1 = acc1 * inv;
    v0 = (v0 > 0.f) ? v0 : expm1f(v0);
    v1 = (v1 > 0.f) ? v1 : expm1f(v1);
    if (SEG) {
        red_add_v2((float*)outh + (size_t)seg[w] * 64 + lane * 2, make_float2(v0, v1));
    } else {
        *(__half2*)((__half*)outh + (size_t)w * 64 + lane * 2) = __floats2half2_rn(v0, v1);
    }
}

// ---------------- atomic edge path (reaction graph only) ----------------
__global__ void edge_fused_kernel(const int* __restrict__ src, const int* __restrict__ dst,
                                  const int* __restrict__ rel,
                                  const float* __restrict__ att_s, const float* __restrict__ att_d,
                                  const __half* __restrict__ hW,
                                  float* __restrict__ dsum, float* __restrict__ agg,
                                  int E, int N)
{
    int t = blockIdx.x * blockDim.x + threadIdx.x;
    int e = t >> 3;
    if (e >= E) return;
    int g = t & 7;
    int s = src[e], d = dst[e], r = rel[e];
    float v = att_s[(size_t)r * N + s] + att_d[(size_t)r * N + d];
    v = (v > 0.f) ? v : 0.2f * v;
    float x = __expf(v);

    uint4 raw = *(const uint4*)&hW[((size_t)r * N + s) * 64 + g * 8];
    __half2* hp = (__half2*)&raw;
    float2 f0 = __half22float2(hp[0]);
    float2 f1 = __half22float2(hp[1]);
    float2 f2 = __half22float2(hp[2]);
    float2 f3 = __half22float2(hp[3]);

    float* base = &agg[(size_t)d * 64 + g * 8];
    red_add_v4(base,     make_float4(x * f0.x, x * f0.y, x * f1.x, x * f1.y));
    red_add_v4(base + 4, make_float4(x * f2.x, x * f2.y, x * f3.x, x * f3.y));
    if (g == 0) atomicAdd(&dsum[d], x);
}

__global__ void norm_elu_seg_kernel(const float* __restrict__ agg, const float* __restrict__ dsum,
                                    const int* __restrict__ seg, float* __restrict__ feat, int n)
{
    int t = blockIdx.x * blockDim.x + threadIdx.x;
    int i = t >> 5;
    if (i >= n) return;
    int g = (t & 31) * 2;
    float s = dsum[i];
    float inv = 1.f / (s + 1e-9f);
    float2 v = *(const float2*)&agg[(size_t)i * 64 + g];
    v.x *= inv; v.y *= inv;
    v.x = (v.x > 0.f) ? v.x : expm1f(v.x);
    v.y = (v.y > 0.f) ? v.y : expm1f(v.y);
    red_add_v2(&feat[(size_t)seg[i] * 128 + g], v);
}

__global__ void segsum_kernel(const float* __restrict__ x, const int* __restrict__ seg,
                              float* __restrict__ out, int n, int ostride, int ooff)
{
    int t = blockIdx.x * blockDim.x + threadIdx.x;
    int i = t >> 4;
    if (i >= n) return;
    int g = (t & 15) * 4;
    int s = seg[i];
    float4 v = *(const float4*)&x[(size_t)i * 64 + g];
    red_add_v4(&out[(size_t)s * ostride + ooff + g], v);
}

// ---------------- MLP head ----------------
__global__ void fc1_kernel(const float* __restrict__ feat, const float* __restrict__ w,
                           const float* __restrict__ b, const float* __restrict__ prelu,
                           float* __restrict__ out)
{
    const int r0 = blockIdx.x * 16;
    const int c0 = blockIdx.y * 128;
    __shared__ float fs[16][128];
    #pragma unroll
    for (int it = 0; it < 4; it++) {
        int idx4 = it * 128 + threadIdx.x;
        int row = idx4 >> 5, col = (idx4 & 31) * 4;
        *(float4*)&fs[row][col] = *(const float4*)&feat[(size_t)(r0 + row) * 128 + col];
    }
    __syncthreads();
    const int col = c0 + threadIdx.x;
    float acc[16];
    #pragma unroll
    for (int j = 0; j < 16; j++) acc[j] = 0.f;
    #pragma unroll 4
    for (int k = 0; k < 128; k++) {
        float wv = w[k * 512 + col];
        #pragma unroll
        for (int j = 0; j < 16; j++) acc[j] += fs[j][k] * wv;
    }
    float bb = b[col], p = prelu[0];
    #pragma unroll
    for (int j = 0; j < 16; j++) {
        float v = acc[j] + bb;
        out[(size_t)(r0 + j) * 512 + col] = (v > 0.f) ? v : p * v;
    }
}

__global__ void fc2_kernel(const float* __restrict__ hid, const float* __restrict__ w,
                           const float* __restrict__ b, float* __restrict__ out)
{
    const int r0 = blockIdx.x * 16;
    const int c0 = blockIdx.y * 128;
    __shared__ float hs[16][512];
    #pragma unroll
    for (int it = 0; it < 16; it++) {
        int idx4 = it * 128 + threadIdx.x;
        int row = idx4 >> 7, col = (idx4 & 127) * 4;
        *(float4*)&hs[row][col] = *(const float4*)&hid[(size_t)(r0 + row) * 512 + col];
    }
    __syncthreads();
    const int col = c0 + threadIdx.x;
    if (col >= DO) return;
    float acc[16];
    #pragma unroll
    for (int j = 0; j < 16; j++) acc[j] = 0.f;
    #pragma unroll 4
    for (int k = 0; k < 512; k++) {
        float wv = w[k * DO + col];
        #pragma unroll
        for (int j = 0; j < 16; j++) acc[j] += hs[j][k] * wv;
    }
    float bb = b[col];
    #pragma unroll
    for (int j = 0; j < 16; j++)
        out[(size_t)(r0 + j) * DO + col] = acc[j] + bb;
}

// ---------------- launch ----------------
static inline int cdiv(int a, int b) { return (a + b - 1) / b; }

extern "C" void kernel_launch(void* const* d_in, const int* in_sizes, int n_in,
                              void* d_out, int out_size)
{
    const float* node_feats = (const float*)d_in[0];
    const int*   edge_src   = (const int*)  d_in[1];
    const int*   edge_dst   = (const int*)  d_in[2];
    const int*   edge_rel   = (const int*)  d_in[3];
    const int*   node2mol   = (const int*)  d_in[4];
    const int*   rxn_src    = (const int*)  d_in[5];
    const int*   rxn_dst    = (const int*)  d_in[6];
    const int*   rxn_rel    = (const int*)  d_in[7];
    const int*   mol2rxn    = (const int*)  d_in[8];
    const float* W1    = (const float*)d_in[9];
    const float* as1   = (const float*)d_in[10];
    const float* ad1   = (const float*)d_in[11];
    const float* W2    = (const float*)d_in[12];
    const float* as2   = (const float*)d_in[13];
    const float* ad2   = (const float*)d_in[14];
    const float* Wr    = (const float*)d_in[15];
    const float* asr   = (const float*)d_in[16];
    const float* adr   = (const float*)d_in[17];
    const float* w_fc1 = (const float*)d_in[18];
    const float* b_fc1 = (const float*)d_in[19];
    const float* prelu = (const float*)d_in[20];
    const float* w_fc2 = (const float*)d_in[21];
    const float* b_fc2 = (const float*)d_in[22];
    float* out = (float*)d_out;

    __half *p_hW, *p_h1;
    float *p_atts, *p_attd, *p_sum, *p_mol, *p_molr, *p_feat, *p_hid;
    int *p_deg, *p_rowptr, *p_cursor, *p_bsum, *p_boff;
    uint32_t* p_epk;
    cudaGetSymbolAddress((void**)&p_hW,    g_hW);
    cudaGetSymbolAddress((void**)&p_h1,    g_h1);
    cudaGetSymbolAddress((void**)&p_atts,  g_atts);
    cudaGetSymbolAddress((void**)&p_attd,  g_attd);
    cudaGetSymbolAddress((void**)&p_sum,   g_sum);
    cudaGetSymbolAddress((void**)&p_deg,   g_deg);
    cudaGetSymbolAddress((void**)&p_rowptr,g_rowptr);
    cudaGetSymbolAddress((void**)&p_cursor,g_cursor);
    cudaGetSymbolAddress((void**)&p_bsum,  g_bsum);
    cudaGetSymbolAddress((void**)&p_boff,  g_boff);
    cudaGetSymbolAddress((void**)&p_epk,   g_epk);
    cudaGetSymbolAddress((void**)&p_mol,   g_mol);
    cudaGetSymbolAddress((void**)&p_molr,  g_molr);
    cudaGetSymbolAddress((void**)&p_feat,  g_feat);
    cudaGetSymbolAddress((void**)&p_hid,   g_hid);

    const int TB = 256;
    const int NBLK = cdiv(NN, 1024);   // 98

    // ===== fork a side stream: CSR build + fills run concurrently with GEMM L1 =====
    cudaStream_t s2;
    cudaStreamCreateWithFlags(&s2, cudaStreamNonBlocking);
    cudaEvent_t ev_fork, ev_join;
    cudaEventCreateWithFlags(&ev_fork, cudaEventDisableTiming);
    cudaEventCreateWithFlags(&ev_join, cudaEventDisableTiming);

    cudaEventRecord(ev_fork, 0);
    cudaStreamWaitEvent(s2, ev_fork, 0);

    // --- side stream: CSR build + zero fills ---
    filli_kernel<<<cdiv(NN, TB), TB, 0, s2>>>(p_deg, 0, NN);
    hist_kernel<<<cdiv(NE, TB), TB, 0, s2>>>(edge_dst, p_deg, NE);
    scan_bsum_kernel<<<NBLK, 256, 0, s2>>>(p_deg, p_bsum, NN);
    scan_sums_kernel<<<1, 128, 0, s2>>>(p_bsum, p_boff, NBLK);
    scan_final_kernel<<<NBLK, 256, 0, s2>>>(p_deg, p_boff, p_rowptr, p_cursor, NN, NBLK);
    scatter_kernel<<<cdiv(NE, TB), TB, 0, s2>>>(edge_src, edge_dst, edge_rel, p_cursor, p_epk, NE);
    fill_all_kernel<<<cdiv(NB * 32 > NM * 16 ? NB * 32 : NM * 16, TB), TB, 0, s2>>>(
        (float4*)p_mol, (float4*)p_molr, (float4*)p_feat, p_sum);
    cudaEventRecord(ev_join, s2);

    // --- main stream: atom layer 1 GEMM (independent of CSR) ---
    hw_mma_kernel<float><<<cdiv(NN, 128), 128>>>(node_feats, W1, as1, ad1,
                                                 p_hW, p_atts, p_attd, NN, RM);
    cudaStreamWaitEvent(0, ev_join, 0);   // join before edge aggregation

    edge_agg_kernel<false><<<cdiv(NN * 32, TB), TB>>>(p_rowptr, p_epk, p_atts, p_attd, p_hW,
                                                      (const int*)0, p_h1, NN, RM);

    // ===== atom layer 2 (reduces straight into mol) =====
    hw_mma_kernel<__half><<<cdiv(NN, 128), 128>>>(p_h1, W2, as2, ad2,
                                                  p_hW, p_atts, p_attd, NN, RM);
    edge_agg_kernel<true><<<cdiv(NN * 32, TB), TB>>>(p_rowptr, p_epk, p_atts, p_attd, p_hW,
                                                     node2mol, p_mol, NN, RM);

    // ===== reaction-level RGAT =====
    hw_mma_kernel<float><<<cdiv(NM, 128), 128>>>(p_mol, Wr, asr, adr,
                                                 p_hW, p_atts, p_attd, NM, RR);
    edge_fused_kernel<<<cdiv(NRE * 8, TB), TB>>>(rxn_src, rxn_dst, rxn_rel,
                                                 p_atts, p_attd, p_hW, p_sum, p_molr, NRE, NM);
    norm_elu_seg_kernel<<<cdiv(NM * 32, TB), TB>>>(p_molr, p_sum, mol2rxn, p_feat, NM);

    // ===== reaction readout (second half: direct mol sums) =====
    segsum_kernel<<<cdiv(NM * 16, TB), TB>>>(p_mol, mol2rxn, p_feat, NM, 128, 64);

    // ===== MLP head =====
    fc1_kernel<<<dim3(NB / 16, 4), 128>>>(p_feat, w_fc1, b_fc1, prelu, p_hid);
    fc2_kernel<<<dim3(NB / 16, 6), 128>>>(p_hid, w_fc2, b_fc2, out);

    cudaEventDestroy(ev_fork);
    cudaEventDestroy(ev_join);
    cudaStreamDestroy(s2);
}

// round 14
// speedup vs baseline: 1.1056x; 1.0276x over previous
#include <cuda_runtime.h>
#include <cuda_fp16.h>
#include <math.h>
#include <stdint.h>

// ---------------- problem constants ----------------
#define NN      100000
#define NE      800000
#define DD      64
#define RM      8
#define NM      5000
#define NRE     40000
#define RR      4
#define NB      1024
#define DH      512
#define DO      703

// ---------------- scratch ----------------
__device__ __half g_hW [(size_t)RM * NN * DD];   // 102.4 MB fp16
__device__ __half g_h1 [(size_t)NN * DD];        // fp16
__device__ __half g_Wh [(2 * RM + RR) * 64 * 64];  // pre-converted fp16 weights W1|W2|Wr
__device__ float g_atts[(size_t)RM * NN];
__device__ float g_attd[(size_t)RM * NN];
__device__ float g_sum [NM];
__device__ int   g_deg   [NN];
__device__ int   g_rowptr[NN + 1];
__device__ int   g_cursor[NN];
__device__ int   g_bsum[128];
__device__ int   g_boff[130];
__device__ uint32_t g_epk[NE];
__device__ float g_mol [(size_t)NM * DD];
__device__ float g_molr[(size_t)NM * DD];
__device__ float g_feat[(size_t)NB * 2 * DD];
__device__ float g_hid [(size_t)NB * DH];

__device__ __forceinline__ void red_add_v4(float* p, float4 v) {
    asm volatile("red.global.add.v4.f32 [%0], {%1,%2,%3,%4};"
                 :: "l"(p), "f"(v.x), "f"(v.y), "f"(v.z), "f"(v.w) : "memory");
}
__device__ __forceinline__ void red_add_v2(float* p, float2 v) {
    asm volatile("red.global.add.v2.f32 [%0], {%1,%2};"
                 :: "l"(p), "f"(v.x), "f"(v.y) : "memory");
}

__global__ void filli_kernel(int* __restrict__ p, int v, int n) {
    int i = blockIdx.x * blockDim.x + threadIdx.x;
    if (i < n) p[i] = v;
}

// pre-convert all weight matrices to fp16 (row-major, same layout)
__global__ void prep_wh_kernel(const float* __restrict__ W1, const float* __restrict__ W2,
                               const float* __restrict__ Wr, __half* __restrict__ Wh)
{
    int i = blockIdx.x * blockDim.x + threadIdx.x;   // 0 .. 20*4096-1
    const int n1 = RM * 4096, n2 = 2 * RM * 4096, n3 = (2 * RM + RR) * 4096;
    float v;
    if (i < n1)       v = W1[i];
    else if (i < n2)  v = W2[i - n1];
    else if (i < n3)  v = Wr[i - n2];
    else return;
    Wh[i] = __float2half(v);
}

#define Z_MOL4   (NM * 16)
#define Z_MOLR4  (NM * 16)
#define Z_FEAT4  (NB * 32)
__global__ void fill_all_kernel(float4* __restrict__ mol, float4* __restrict__ molr,
                                float4* __restrict__ feat, float* __restrict__ sum)
{
    int i = blockIdx.x * blockDim.x + threadIdx.x;
    float4 z = make_float4(0.f, 0.f, 0.f, 0.f);
    if (i < Z_MOL4) mol[i] = z;
    if (i < Z_MOLR4) molr[i] = z;
    if (i < Z_FEAT4) feat[i] = z;
    if (i < NM) sum[i] = 0.f;
}

// ================= CSR build =================
__global__ void hist_kernel(const int* __restrict__ dst, int* __restrict__ deg, int E) {
    int e = blockIdx.x * blockDim.x + threadIdx.x;
    if (e < E) atomicAdd(&deg[dst[e]], 1);
}

__global__ void scan_bsum_kernel(const int* __restrict__ deg, int* __restrict__ bsum, int N) {
    int b = blockIdx.x, t = threadIdx.x;
    int base = b * 1024 + t;
    int s = 0;
    #pragma unroll
    for (int q = 0; q < 4; q++) { int i = base + q * 256; if (i < N) s += deg[i]; }
    #pragma unroll
    for (int o = 16; o; o >>= 1) s += __shfl_xor_sync(0xffffffffu, s, o);
    __shared__ int ws[8];
    if ((t & 31) == 0) ws[t >> 5] = s;
    __syncthreads();
    if (t == 0) { int tot = 0; for (int i = 0; i < 8; i++) tot += ws[i]; bsum[b] = tot; }
}

__global__ void scan_sums_kernel(const int* __restrict__ bsum, int* __restrict__ boff, int nb) {
    int t = threadIdx.x, lane = t & 31, w = t >> 5;
    int v = (t < nb) ? bsum[t] : 0;
    int inc = v;
    #pragma unroll
    for (int o = 1; o < 32; o <<= 1) {
        int nv = __shfl_up_sync(0xffffffffu, inc, o);
        if (lane >= o) inc += nv;
    }
    __shared__ int ws[4];
    if (lane == 31) ws[w] = inc;
    __syncthreads();
    int add = 0;
    for (int i = 0; i < w; i++) add += ws[i];
    if (t < nb) boff[t] = add + inc - v;
    if (t == 0) boff[nb] = ws[0] + ws[1] + ws[2] + ws[3];
}

__global__ void scan_final_kernel(const int* __restrict__ deg, const int* __restrict__ boff,
                                  int* __restrict__ rowptr, int* __restrict__ cursor, int N, int nb) {
    int b = blockIdx.x, t = threadIdx.x, lane = t & 31, wid = t >> 5;
    int idx0 = b * 1024 + t * 4;
    int v0 = 0, v1 = 0, v2 = 0, v3 = 0;
    if (idx0 + 0 < N) v0 = deg[idx0 + 0];
    if (idx0 + 1 < N) v1 = deg[idx0 + 1];
    if (idx0 + 2 < N) v2 = deg[idx0 + 2];
    if (idx0 + 3 < N) v3 = deg[idx0 + 3];
    int tot = v0 + v1 + v2 + v3;
    int inc = tot;
    #pragma unroll
    for (int o = 1; o < 32; o <<= 1) {
        int nv = __shfl_up_sync(0xffffffffu, inc, o);
        if (lane >= o) inc += nv;
    }
    __shared__ int wsum[8], woff[8];
    if (lane == 31) wsum[wid] = inc;
    __syncthreads();
    if (t == 0) { int a = 0; for (int i = 0; i < 8; i++) { woff[i] = a; a += wsum[i]; } }
    __syncthreads();
    int run = boff[b] + woff[wid] + inc - tot;
    if (idx0 + 0 < N) { rowptr[idx0 + 0] = run; cursor[idx0 + 0] = run; } run += v0;
    if (idx0 + 1 < N) { rowptr[idx0 + 1] = run; cursor[idx0 + 1] = run; } run += v1;
    if (idx0 + 2 < N) { rowptr[idx0 + 2] = run; cursor[idx0 + 2] = run; } run += v2;
    if (idx0 + 3 < N) { rowptr[idx0 + 3] = run; cursor[idx0 + 3] = run; }
    if (b == 0 && t == 0) rowptr[N] = boff[nb];
}

__global__ void scatter_kernel(const int* __restrict__ src, const int* __restrict__ dst,
                               const int* __restrict__ rel,
                               int* __restrict__ cursor, uint32_t* __restrict__ epk, int E) {
    int e = blockIdx.x * blockDim.x + threadIdx.x;
    if (e >= E) return;
    int pos = atomicAdd(&cursor[dst[e]], 1);
    epk[pos] = (uint32_t)src[e] | ((uint32_t)rel[e] << 20);
}

// ================= warp-MMA helpers =================
__device__ __forceinline__ uint32_t smem_u32(const void* p) {
    return (uint32_t)__cvta_generic_to_shared(p);
}
#define LDSM_X4(r0, r1, r2, r3, addr) \
    asm volatile("ldmatrix.sync.aligned.m8n8.x4.shared.b16 {%0,%1,%2,%3}, [%4];" \
                 : "=r"(r0), "=r"(r1), "=r"(r2), "=r"(r3) : "r"(addr))
#define LDSM_X2T(r0, r1, addr) \
    asm volatile("ldmatrix.sync.aligned.m8n8.x2.trans.shared.b16 {%0,%1}, [%2];" \
                 : "=r"(r0), "=r"(r1) : "r"(addr))
#define MMA16816(c, a, b) \
    asm volatile("mma.sync.aligned.m16n8k16.row.col.f32.f16.f16.f32 " \
                 "{%0,%1,%2,%3}, {%4,%5,%6,%7}, {%8,%9}, {%0,%1,%2,%3};" \
                 : "+f"((c)[0]), "+f"((c)[1]), "+f"((c)[2]), "+f"((c)[3]) \
                 : "r"((a)[0]), "r"((a)[1]), "r"((a)[2]), "r"((a)[3]), \
                   "r"((b)[0]), "r"((b)[1]))
#define CP_ASYNC16(dst, src) \
    asm volatile("cp.async.ca.shared.global [%0], [%1], 16;" :: "r"(dst), "l"(src) : "memory")
#define CP_COMMIT()  asm volatile("cp.async.commit_group;" ::: "memory")
#define CP_WAIT0()   asm volatile("cp.async.wait_group 0;" ::: "memory")

// ---------------- hW GEMM on HMMA + fused attention-logit epilogue ----------------
// W tiles arrive via cp.async from pre-converted fp16 weights (double-buffered).
template<typename TIN>
__global__ __launch_bounds__(128)
void hw_mma_kernel(const TIN* __restrict__ h,
                   const __half* __restrict__ Wh,
                   const float* __restrict__ a_src,
                   const float* __restrict__ a_dst,
                   __half* __restrict__ hW,
                   float* __restrict__ att_s,
                   float* __restrict__ att_d,
                   int N, int R)
{
    __shared__ __align__(16) __half sa [128 * 72];   // h tile, then output staging
    __shared__ __align__(16) __half swt[2][64 * 72];
    __shared__ float sas[8 * 64], sad[8 * 64];

    const int tid  = threadIdx.x;
    const int wid  = tid >> 5;
    const int lane = tid & 31;
    const int n0   = blockIdx.x * 128;

    // kick off W_0 tile copy first (hides behind h-tile load)
    {
        #pragma unroll
        for (int it = 0; it < 4; it++) {
            int chunk = it * 128 + tid;         // 0..511
            int k = chunk >> 3, c8 = (chunk & 7) * 8;
            CP_ASYNC16(smem_u32(&swt[0][k * 72 + c8]), Wh + k * 64 + c8);
        }
        CP_COMMIT();
    }

    for (int i = tid; i < R * 64; i += 128) { sas[i] = a_src[i]; sad[i] = a_dst[i]; }

    #pragma unroll
    for (int it = 0; it < 8; it++) {
        int chunk = it * 128 + tid;
        int row = chunk >> 3;
        int c8  = (chunk & 7) * 8;
        int n = n0 + row;
        if (sizeof(TIN) == 4) {
            float4 a = make_float4(0.f,0.f,0.f,0.f), b = a;
            if (n < N) {
                a = *(const float4*)((const float*)h + (size_t)n * 64 + c8);
                b = *(const float4*)((const float*)h + (size_t)n * 64 + c8 + 4);
            }
            __half2 pk[4];
            pk[0] = __floats2half2_rn(a.x, a.y);
            pk[1] = __floats2half2_rn(a.z, a.w);
            pk[2] = __floats2half2_rn(b.x, b.y);
            pk[3] = __floats2half2_rn(b.z, b.w);
            *(uint4*)&sa[row * 72 + c8] = *(uint4*)pk;
        } else {
            uint4 v = make_uint4(0u, 0u, 0u, 0u);
            if (n < N) v = *(const uint4*)((const __half*)h + (size_t)n * 64 + c8);
            *(uint4*)&sa[row * 72 + c8] = v;
        }
    }
    CP_WAIT0();
    __syncthreads();

    uint32_t afrag[2][4][4];
    {
        const int l15 = lane & 15;
        const int lhi = lane >> 4;
        #pragma unroll
        for (int mt = 0; mt < 2; mt++)
            #pragma unroll
            for (int kk = 0; kk < 4; kk++) {
                uint32_t addr = smem_u32(&sa[(wid * 32 + mt * 16 + l15) * 72 + kk * 16 + lhi * 8]);
                LDSM_X4(afrag[mt][kk][0], afrag[mt][kk][1],
                        afrag[mt][kk][2], afrag[mt][kk][3], addr);
            }
    }

    const int t4 = lane >> 2;
    const int t2 = (lane & 3) * 2;

    for (int r = 0; r < R; r++) {
        const int buf = r & 1;

        float c[2][8][4];
        #pragma unroll
        for (int mt = 0; mt < 2; mt++)
            #pragma unroll
            for (int j = 0; j < 8; j++)
                #pragma unroll
                for (int q = 0; q < 4; q++) c[mt][j][q] = 0.f;

        #pragma unroll
        for (int kk = 0; kk < 4; kk++) {
            uint32_t b[8][2];
            const int l15 = lane & 15;
            #pragma unroll
            for (int j = 0; j < 8; j++) {
                uint32_t addr = smem_u32(&swt[buf][(kk * 16 + l15) * 72 + j * 8]);
                LDSM_X2T(b[j][0], b[j][1], addr);
            }
            #pragma unroll
            for (int mt = 0; mt < 2; mt++)
                #pragma unroll
                for (int j = 0; j < 8; j++)
                    MMA16816(c[mt][j], afrag[mt][kk], b[j]);
        }

        // prefetch next relation's fp16 W tile via cp.async
        if (r + 1 < R) {
            const __half* Wn = Wh + (size_t)(r + 1) * 4096;
            #pragma unroll
            for (int it = 0; it < 4; it++) {
                int chunk = it * 128 + tid;
                int k = chunk >> 3, c8 = (chunk & 7) * 8;
                CP_ASYNC16(smem_u32(&swt[1 - buf][k * 72 + c8]), Wn + k * 64 + c8);
            }
            CP_COMMIT();
        }

        #pragma unroll
        for (int mt = 0; mt < 2; mt++) {
            float ps0 = 0.f, pd0 = 0.f, ps1 = 0.f, pd1 = 0.f;
            #pragma unroll
            for (int j = 0; j < 8; j++) {
                float as0 = sas[r * 64 + j * 8 + t2], as1 = sas[r * 64 + j * 8 + t2 + 1];
                float ad0 = sad[r * 64 + j * 8 + t2], ad1 = sad[r * 64 + j * 8 + t2 + 1];
                ps0 += c[mt][j][0] * as0 + c[mt][j][1] * as1;
                pd0 += c[mt][j][0] * ad0 + c[mt][j][1] * ad1;
                ps1 += c[mt][j][2] * as0 + c[mt][j][3] * as1;
                pd1 += c[mt][j][2] * ad0 + c[mt][j][3] * ad1;
            }
            #pragma unroll
            for (int o = 1; o <= 2; o <<= 1) {
                ps0 += __shfl_xor_sync(0xffffffffu, ps0, o);
                pd0 += __shfl_xor_sync(0xffffffffu, pd0, o);
                ps1 += __shfl_xor_sync(0xffffffffu, ps1, o);
                pd1 += __shfl_xor_sync(0xffffffffu, pd1, o);
            }
            if ((lane & 3) == 0) {
                int n1 = n0 + wid * 32 + mt * 16 + t4;
                int n2 = n1 + 8;
                if (n1 < N) { att_s[(size_t)r * N + n1] = ps0; att_d[(size_t)r * N + n1] = pd0; }
                if (n2 < N) { att_s[(size_t)r * N + n2] = ps1; att_d[(size_t)r * N + n2] = pd1; }
            }
        }

        #pragma unroll
        for (int mt = 0; mt < 2; mt++) {
            int rr = wid * 32 + mt * 16 + t4;
            #pragma unroll
            for (int j = 0; j < 8; j++) {
                *(__half2*)&sa[rr * 72 + j * 8 + t2]       = __floats2half2_rn(c[mt][j][0], c[mt][j][1]);
                *(__half2*)&sa[(rr + 8) * 72 + j * 8 + t2] = __floats2half2_rn(c[mt][j][2], c[mt][j][3]);
            }
        }
        __syncwarp();
        #pragma unroll
        for (int it = 0; it < 8; it++) {
            int idx = it * 32 + lane;
            int rowl = idx >> 3;
            int q    = idx & 7;
            int row  = wid * 32 + rowl;
            int n = n0 + row;
            if (n < N)
                *(uint4*)&hW[((size_t)r * N + n) * 64 + q * 8] = *(uint4*)&sa[row * 72 + q * 8];
        }
        CP_WAIT0();
        __syncthreads();
    }
}

// ---------------- CSR edge aggregation ----------------
template<bool SEG>
__global__ void edge_agg_kernel(const int* __restrict__ rowptr, const uint32_t* __restrict__ epk,
                                const float* __restrict__ att_s, const float* __restrict__ att_d,
                                const __half* __restrict__ hW, const int* __restrict__ seg,
                                void* __restrict__ outh, int N, int R)
{
    int w = (blockIdx.x * blockDim.x + threadIdx.x) >> 5;
    int lane = threadIdx.x & 31;
    if (w >= N) return;
    int beg = rowptr[w], end = rowptr[w + 1];
    float adv = (lane < R) ? att_d[(size_t)lane * N + w] : 0.f;
    float acc0 = 0.f, acc1 = 0.f, ssum = 0.f;
    int e = beg;
    for (; e + 3 < end; e += 4) {
        uint32_t p0 = epk[e], p1 = epk[e + 1], p2 = epk[e + 2], p3 = epk[e + 3];
        int s0 = p0 & 0xFFFFF, r0 = p0 >> 20;
        int s1 = p1 & 0xFFFFF, r1 = p1 >> 20;
        int s2 = p2 & 0xFFFFF, r2 = p2 >> 20;
        int s3 = p3 & 0xFFFFF, r3 = p3 >> 20;
        float sc0 = att_s[(size_t)r0 * N + s0] + __shfl_sync(0xffffffffu, adv, r0);
        float sc1 = att_s[(size_t)r1 * N + s1] + __shfl_sync(0xffffffffu, adv, r1);
        float sc2 = att_s[(size_t)r2 * N + s2] + __shfl_sync(0xffffffffu, adv, r2);
        float sc3 = att_s[(size_t)r3 * N + s3] + __shfl_sync(0xffffffffu, adv, r3);
        sc0 = (sc0 > 0.f) ? sc0 : 0.2f * sc0;
        sc1 = (sc1 > 0.f) ? sc1 : 0.2f * sc1;
        sc2 = (sc2 > 0.f) ? sc2 : 0.2f * sc2;
        sc3 = (sc3 > 0.f) ? sc3 : 0.2f * sc3;
        float x0 = __expf(sc0), x1 = __expf(sc1), x2 = __expf(sc2), x3 = __expf(sc3);
        __half2 h0 = *(const __half2*)&hW[((size_t)r0 * N + s0) * 64 + lane * 2];
        __half2 h1 = *(const __half2*)&hW[((size_t)r1 * N + s1) * 64 + lane * 2];
        __half2 h2 = *(const __half2*)&hW[((size_t)r2 * N + s2) * 64 + lane * 2];
        __half2 h3 = *(const __half2*)&hW[((size_t)r3 * N + s3) * 64 + lane * 2];
        float2 f0 = __half22float2(h0), f1 = __half22float2(h1);
        float2 f2 = __half22float2(h2), f3 = __half22float2(h3);
        acc0 = fmaf(x0, f0.x, acc0); acc1 = fmaf(x0, f0.y, acc1);
        acc0 = fmaf(x1, f1.x, acc0); acc1 = fmaf(x1, f1.y, acc1);
        acc0 = fmaf(x2, f2.x, acc0); acc1 = fmaf(x2, f2.y, acc1);
        acc0 = fmaf(x3, f3.x, acc0); acc1 = fmaf(x3, f3.y, acc1);
        ssum += (x0 + x1) + (x2 + x3);
    }
    for (; e < end; e++) {
        uint32_t p0 = epk[e];
        int s0 = p0 & 0xFFFFF, r0 = p0 >> 20;
        float sc0 = att_s[(size_t)r0 * N + s0] + __shfl_sync(0xffffffffu, adv, r0);
        sc0 = (sc0 > 0.f) ? sc0 : 0.2f * sc0;
        float x0 = __expf(sc0);
        __half2 h0 = *(const __half2*)&hW[((size_t)r0 * N + s0) * 64 + lane * 2];
        float2 f0 = __half22float2(h0);
        acc0 = fmaf(x0, f0.x, acc0); acc1 = fmaf(x0, f0.y, acc1);
        ssum += x0;
    }
    float inv = 1.f / (ssum + 1e-9f);
    float v0 = acc0 * inv, v1 = acc1 * inv;
    v0 = (v0 > 0.f) ? v0 : expm1f(v0);
    v1 = (v1 > 0.f) ? v1 : expm1f(v1);
    if (SEG) {
        red_add_v2((float*)outh + (size_t)seg[w] * 64 + lane * 2, make_float2(v0, v1));
    } else {
        *(__half2*)((__half*)outh + (size_t)w * 64 + lane * 2) = __floats2half2_rn(v0, v1);
    }
}

// ---------------- atomic edge path (reaction graph only) ----------------
__global__ void edge_fused_kernel(const int* __restrict__ src, const int* __restrict__ dst,
                                  const int* __restrict__ rel,
                                  const float* __restrict__ att_s, const float* __restrict__ att_d,
                                  const __half* __restrict__ hW,
                                  float* __restrict__ dsum, float* __restrict__ agg,
                                  int E, int N)
{
    int t = blockIdx.x * blockDim.x + threadIdx.x;
    int e = t >> 3;
    if (e >= E) return;
    int g = t & 7;
    int s = src[e], d = dst[e], r = rel[e];
    float v = att_s[(size_t)r * N + s] + att_d[(size_t)r * N + d];
    v = (v > 0.f) ? v : 0.2f * v;
    float x = __expf(v);

    uint4 raw = *(const uint4*)&hW[((size_t)r * N + s) * 64 + g * 8];
    __half2* hp = (__half2*)&raw;
    float2 f0 = __half22float2(hp[0]);
    float2 f1 = __half22float2(hp[1]);
    float2 f2 = __half22float2(hp[2]);
    float2 f3 = __half22float2(hp[3]);

    float* base = &agg[(size_t)d * 64 + g * 8];
    red_add_v4(base,     make_float4(x * f0.x, x * f0.y, x * f1.x, x * f1.y));
    red_add_v4(base + 4, make_float4(x * f2.x, x * f2.y, x * f3.x, x * f3.y));
    if (g == 0) atomicAdd(&dsum[d], x);
}

__global__ void norm_elu_seg_kernel(const float* __restrict__ agg, const float* __restrict__ dsum,
                                    const int* __restrict__ seg, float* __restrict__ feat, int n)
{
    int t = blockIdx.x * blockDim.x + threadIdx.x;
    int i = t >> 5;
    if (i >= n) return;
    int g = (t & 31) * 2;
    float s = dsum[i];
    float inv = 1.f / (s + 1e-9f);
    float2 v = *(const float2*)&agg[(size_t)i * 64 + g];
    v.x *= inv; v.y *= inv;
    v.x = (v.x > 0.f) ? v.x : expm1f(v.x);
    v.y = (v.y > 0.f) ? v.y : expm1f(v.y);
    red_add_v2(&feat[(size_t)seg[i] * 128 + g], v);
}

__global__ void segsum_kernel(const float* __restrict__ x, const int* __restrict__ seg,
                              float* __restrict__ out, int n, int ostride, int ooff)
{
    int t = blockIdx.x * blockDim.x + threadIdx.x;
    int i = t >> 4;
    if (i >= n) return;
    int g = (t & 15) * 4;
    int s = seg[i];
    float4 v = *(const float4*)&x[(size_t)i * 64 + g];
    red_add_v4(&out[(size_t)s * ostride + ooff + g], v);
}

// ---------------- MLP head ----------------
__global__ void fc1_kernel(const float* __restrict__ feat, const float* __restrict__ w,
                           const float* __restrict__ b, const float* __restrict__ prelu,
                           float* __restrict__ out)
{
    const int r0 = blockIdx.x * 16;
    const int c0 = blockIdx.y * 128;
    __shared__ float fs[16][128];
    #pragma unroll
    for (int it = 0; it < 4; it++) {
        int idx4 = it * 128 + threadIdx.x;
        int row = idx4 >> 5, col = (idx4 & 31) * 4;
        *(float4*)&fs[row][col] = *(const float4*)&feat[(size_t)(r0 + row) * 128 + col];
    }
    __syncthreads();
    const int col = c0 + threadIdx.x;
    float acc[16];
    #pragma unroll
    for (int j = 0; j < 16; j++) acc[j] = 0.f;
    #pragma unroll 4
    for (int k = 0; k < 128; k++) {
        float wv = w[k * 512 + col];
        #pragma unroll
        for (int j = 0; j < 16; j++) acc[j] += fs[j][k] * wv;
    }
    float bb = b[col], p = prelu[0];
    #pragma unroll
    for (int j = 0; j < 16; j++) {
        float v = acc[j] + bb;
        out[(size_t)(r0 + j) * 512 + col] = (v > 0.f) ? v : p * v;
    }
}

__global__ void fc2_kernel(const float* __restrict__ hid, const float* __restrict__ w,
                           const float* __restrict__ b, float* __restrict__ out)
{
    const int r0 = blockIdx.x * 16;
    const int c0 = blockIdx.y * 128;
    __shared__ float hs[16][512];
    #pragma unroll
    for (int it = 0; it < 16; it++) {
        int idx4 = it * 128 + threadIdx.x;
        int row = idx4 >> 7, col = (idx4 & 127) * 4;
        *(float4*)&hs[row][col] = *(const float4*)&hid[(size_t)(r0 + row) * 512 + col];
    }
    __syncthreads();
    const int col = c0 + threadIdx.x;
    if (col >= DO) return;
    float acc[16];
    #pragma unroll
    for (int j = 0; j < 16; j++) acc[j] = 0.f;
    #pragma unroll 4
    for (int k = 0; k < 512; k++) {
        float wv = w[k * DO + col];
        #pragma unroll
        for (int j = 0; j < 16; j++) acc[j] += hs[j][k] * wv;
    }
    float bb = b[col];
    #pragma unroll
    for (int j = 0; j < 16; j++)
        out[(size_t)(r0 + j) * DO + col] = acc[j] + bb;
}

// ---------------- launch ----------------
static inline int cdiv(int a, int b) { return (a + b - 1) / b; }

extern "C" void kernel_launch(void* const* d_in, const int* in_sizes, int n_in,
                              void* d_out, int out_size)
{
    const float* node_feats = (const float*)d_in[0];
    const int*   edge_src   = (const int*)  d_in[1];
    const int*   edge_dst   = (const int*)  d_in[2];
    const int*   edge_rel   = (const int*)  d_in[3];
    const int*   node2mol   = (const int*)  d_in[4];
    const int*   rxn_src    = (const int*)  d_in[5];
    const int*   rxn_dst    = (const int*)  d_in[6];
    const int*   rxn_rel    = (const int*)  d_in[7];
    const int*   mol2rxn    = (const int*)  d_in[8];
    const float* W1    = (const float*)d_in[9];
    const float* as1   = (const float*)d_in[10];
    const float* ad1   = (const float*)d_in[11];
    const float* W2    = (const float*)d_in[12];
    const float* as2   = (const float*)d_in[13];
    const float* ad2   = (const float*)d_in[14];
    const float* Wr    = (const float*)d_in[15];
    const float* asr   = (const float*)d_in[16];
    const float* adr   = (const float*)d_in[17];
    const float* w_fc1 = (const float*)d_in[18];
    const float* b_fc1 = (const float*)d_in[19];
    const float* prelu = (const float*)d_in[20];
    const float* w_fc2 = (const float*)d_in[21];
    const float* b_fc2 = (const float*)d_in[22];
    float* out = (float*)d_out;

    __half *p_hW, *p_h1, *p_Wh;
    float *p_atts, *p_attd, *p_sum, *p_mol, *p_molr, *p_feat, *p_hid;
    int *p_deg, *p_rowptr, *p_cursor, *p_bsum, *p_boff;
    uint32_t* p_epk;
    cudaGetSymbolAddress((void**)&p_hW,    g_hW);
    cudaGetSymbolAddress((void**)&p_h1,    g_h1);
    cudaGetSymbolAddress((void**)&p_Wh,    g_Wh);
    cudaGetSymbolAddress((void**)&p_atts,  g_atts);
    cudaGetSymbolAddress((void**)&p_attd,  g_attd);
    cudaGetSymbolAddress((void**)&p_sum,   g_sum);
    cudaGetSymbolAddress((void**)&p_deg,   g_deg);
    cudaGetSymbolAddress((void**)&p_rowptr,g_rowptr);
    cudaGetSymbolAddress((void**)&p_cursor,g_cursor);
    cudaGetSymbolAddress((void**)&p_bsum,  g_bsum);
    cudaGetSymbolAddress((void**)&p_boff,  g_boff);
    cudaGetSymbolAddress((void**)&p_epk,   g_epk);
    cudaGetSymbolAddress((void**)&p_mol,   g_mol);
    cudaGetSymbolAddress((void**)&p_molr,  g_molr);
    cudaGetSymbolAddress((void**)&p_feat,  g_feat);
    cudaGetSymbolAddress((void**)&p_hid,   g_hid);

    const int TB = 256;
    const int NBLK = cdiv(NN, 1024);   // 98
    const int WH_N = (2 * RM + RR) * 4096;

    // ===== pre-convert weights (tiny, main stream) =====
    prep_wh_kernel<<<cdiv(WH_N, TB), TB>>>(W1, W2, Wr, p_Wh);

    // ===== fork side stream: CSR build + fills concurrent with GEMM L1 =====
    cudaStream_t s2;
    cudaStreamCreateWithFlags(&s2, cudaStreamNonBlocking);
    cudaEvent_t ev_fork, ev_join, ev_mol, ev_seg;
    cudaEventCreateWithFlags(&ev_fork, cudaEventDisableTiming);
    cudaEventCreateWithFlags(&ev_join, cudaEventDisableTiming);
    cudaEventCreateWithFlags(&ev_mol,  cudaEventDisableTiming);
    cudaEventCreateWithFlags(&ev_seg,  cudaEventDisableTiming);

    cudaEventRecord(ev_fork, 0);
    cudaStreamWaitEvent(s2, ev_fork, 0);

    filli_kernel<<<cdiv(NN, TB), TB, 0, s2>>>(p_deg, 0, NN);
    hist_kernel<<<cdiv(NE, TB), TB, 0, s2>>>(edge_dst, p_deg, NE);
    scan_bsum_kernel<<<NBLK, 256, 0, s2>>>(p_deg, p_bsum, NN);
    scan_sums_kernel<<<1, 128, 0, s2>>>(p_bsum, p_boff, NBLK);
    scan_final_kernel<<<NBLK, 256, 0, s2>>>(p_deg, p_boff, p_rowptr, p_cursor, NN, NBLK);
    scatter_kernel<<<cdiv(NE, TB), TB, 0, s2>>>(edge_src, edge_dst, edge_rel, p_cursor, p_epk, NE);
    fill_all_kernel<<<cdiv(NB * 32 > NM * 16 ? NB * 32 : NM * 16, TB), TB, 0, s2>>>(
        (float4*)p_mol, (float4*)p_molr, (float4*)p_feat, p_sum);
    cudaEventRecord(ev_join, s2);

    // --- main stream: atom layer 1 ---
    hw_mma_kernel<float><<<cdiv(NN, 128), 128>>>(node_feats, p_Wh, as1, ad1,
                                                 p_hW, p_atts, p_attd, NN, RM);
    cudaStreamWaitEvent(0, ev_join, 0);
    edge_agg_kernel<false><<<cdiv(NN * 32, TB), TB>>>(p_rowptr, p_epk, p_atts, p_attd, p_hW,
                                                      (const int*)0, p_h1, NN, RM);

    // ===== atom layer 2 (reduces straight into mol) =====
    hw_mma_kernel<__half><<<cdiv(NN, 128), 128>>>(p_h1, p_Wh + (size_t)RM * 4096, as2, ad2,
                                                  p_hW, p_atts, p_attd, NN, RM);
    edge_agg_kernel<true><<<cdiv(NN * 32, TB), TB>>>(p_rowptr, p_epk, p_atts, p_attd, p_hW,
                                                     node2mol, p_mol, NN, RM);
    cudaEventRecord(ev_mol, 0);

    // --- side stream: direct mol sums into feat[:,64:] overlap with reaction GEMM ---
    cudaStreamWaitEvent(s2, ev_mol, 0);
    segsum_kernel<<<cdiv(NM * 16, TB), TB, 0, s2>>>(p_mol, mol2rxn, p_feat, NM, 128, 64);
    cudaEventRecord(ev_seg, s2);

    // ===== reaction-level RGAT (main) =====
    hw_mma_kernel<float><<<cdiv(NM, 128), 128>>>(p_mol, p_Wh + (size_t)2 * RM * 4096, asr, adr,
                                                 p_hW, p_atts, p_attd, NM, RR);
    edge_fused_kernel<<<cdiv(NRE * 8, TB), TB>>>(rxn_src, rxn_dst, rxn_rel,
                                                 p_atts, p_attd, p_hW, p_sum, p_molr, NRE, NM);
    norm_elu_seg_kernel<<<cdiv(NM * 32, TB), TB>>>(p_molr, p_sum, mol2rxn, p_feat, NM);
    cudaStreamWaitEvent(0, ev_seg, 0);

    // ===== MLP head =====
    fc1_kernel<<<dim3(NB / 16, 4), 128>>>(p_feat, w_fc1, b_fc1, prelu, p_hid);
    fc2_kernel<<<dim3(NB / 16, 6), 128>>>(p_hid, w_fc2, b_fc2, out);

    cudaEventDestroy(ev_fork);
    cudaEventDestroy(ev_join);
    cudaEventDestroy(ev_mol);
    cudaEventDestroy(ev_seg);
    cudaStreamDestroy(s2);
}